// round 4
// baseline (speedup 1.0000x reference)
#include <cuda_runtime.h>
#include <math.h>

// Problem constants
#define BATCH 4
#define SEQ   2048
#define HIDD  1024
#define NH    16
#define HD    64

// GEMM config: C[M,N] = A[M,K] @ W[K,N], M=8192, N=K=1024
#define GM (BATCH*SEQ)
#define GK HIDD
#define GN HIDD
#define BM 128
#define BN 128
#define BKK 16
#define TM 8
#define TN 8

// Flash attention tiles
#define BQ  64
#define BKV 64

// Scratch (allocations are forbidden; __device__ globals are the sanctioned path)
__device__ float g_Q[BATCH*SEQ*HIDD];
__device__ float g_K[BATCH*SEQ*HIDD];
__device__ float g_V[BATCH*SEQ*HIDD];
__device__ float g_O[BATCH*SEQ*HIDD];

// ---------------------------------------------------------------------------
// SGEMM body: 128x128 block, 256 threads, 8x8 per-thread microtile, BK=16.
// A staged transposed (As[k][m]) so the inner loop is pure outer-product FFMA
// with broadcast/vector LDS.128 reads.
// ---------------------------------------------------------------------------
__device__ __forceinline__ void gemm_body(const float* __restrict__ A,
                                          const float* __restrict__ W,
                                          float* __restrict__ C)
{
    __shared__ float As[BKK][BM];
    __shared__ float Bs[BKK][BN];

    const int tid = threadIdx.x;
    const int bm  = blockIdx.y * BM;
    const int bn  = blockIdx.x * BN;
    const int ty  = tid >> 4;      // 0..15 -> rows ty*8..ty*8+7
    const int tx  = tid & 15;      // 0..15 -> cols tx*8..tx*8+7

    float acc[TM][TN];
#pragma unroll
    for (int i = 0; i < TM; i++)
#pragma unroll
        for (int j = 0; j < TN; j++) acc[i][j] = 0.0f;

    for (int k0 = 0; k0 < GK; k0 += BKK) {
        // Stage A tile (128x16) transposed: 512 float4 loads, 2 per thread
#pragma unroll
        for (int t = 0; t < 2; t++) {
            int idx = tid + t * 256;
            int r = idx >> 2;              // 0..127
            int c = (idx & 3) << 2;        // 0,4,8,12
            float4 a = *(const float4*)(A + (size_t)(bm + r) * GK + k0 + c);
            As[c + 0][r] = a.x;
            As[c + 1][r] = a.y;
            As[c + 2][r] = a.z;
            As[c + 3][r] = a.w;
        }
        // Stage W tile (16x128): natural layout, coalesced float4
#pragma unroll
        for (int t = 0; t < 2; t++) {
            int idx = tid + t * 256;
            int r = idx >> 5;              // 0..15
            int c = (idx & 31) << 2;       // 0..124
            *(float4*)(&Bs[r][c]) = *(const float4*)(W + (size_t)(k0 + r) * GN + bn + c);
        }
        __syncthreads();

#pragma unroll
        for (int kk = 0; kk < BKK; kk++) {
            float a[TM], b[TN];
            float4 a0 = *(const float4*)(&As[kk][ty * TM]);
            float4 a1 = *(const float4*)(&As[kk][ty * TM + 4]);
            float4 b0 = *(const float4*)(&Bs[kk][tx * TN]);
            float4 b1 = *(const float4*)(&Bs[kk][tx * TN + 4]);
            a[0]=a0.x; a[1]=a0.y; a[2]=a0.z; a[3]=a0.w;
            a[4]=a1.x; a[5]=a1.y; a[6]=a1.z; a[7]=a1.w;
            b[0]=b0.x; b[1]=b0.y; b[2]=b0.z; b[3]=b0.w;
            b[4]=b1.x; b[5]=b1.y; b[6]=b1.z; b[7]=b1.w;
#pragma unroll
            for (int i = 0; i < TM; i++)
#pragma unroll
                for (int j = 0; j < TN; j++)
                    acc[i][j] = fmaf(a[i], b[j], acc[i][j]);
        }
        __syncthreads();
    }

#pragma unroll
    for (int i = 0; i < TM; i++) {
        float* cp = C + (size_t)(bm + ty * TM + i) * GN + bn + tx * TN;
        *(float4*)(cp)     = make_float4(acc[i][0], acc[i][1], acc[i][2], acc[i][3]);
        *(float4*)(cp + 4) = make_float4(acc[i][4], acc[i][5], acc[i][6], acc[i][7]);
    }
}

// Fused Q/K/V projections: grid.z picks the (input, weight, output) triple.
__global__ void __launch_bounds__(256, 2) qkv_gemm_kernel(
    const float* __restrict__ q, const float* __restrict__ k, const float* __restrict__ v,
    const float* __restrict__ Wq, const float* __restrict__ Wk, const float* __restrict__ Wv)
{
    const float* A; const float* W; float* C;
    if (blockIdx.z == 0)      { A = q; W = Wq; C = g_Q; }
    else if (blockIdx.z == 1) { A = k; W = Wk; C = g_K; }
    else                      { A = v; W = Wv; C = g_V; }
    gemm_body(A, W, C);
}

__global__ void __launch_bounds__(256, 2) out_gemm_kernel(
    const float* __restrict__ Wo, float* __restrict__ out)
{
    gemm_body(g_O, Wo, out);
}

// ---------------------------------------------------------------------------
// Flash attention: one CTA per (b, h, 64-query tile); streams 64-key tiles
// with online softmax. D=64 resident. Transposed+swizzled SMEM layout:
// element (d, r) lives at d*64 + (r ^ (d & 28)) -> staging stores <=2-way
// conflicted AND compute loads are contiguous float4 (LDS.128).
// ---------------------------------------------------------------------------
__device__ __forceinline__ int swz(int d, int r) {
    return d * 64 + (r ^ (d & 28));
}

__global__ void __launch_bounds__(256) flash_kernel()
{
    extern __shared__ float sm[];
    float* Qt = sm;               // [d][r] swizzled, 4096 floats (pre-scaled)
    float* Kt = Qt + 4096;        // [d][c] swizzled
    float* Pt = Kt + 4096;        // [c][r] swizzled
    float* Vs = Pt + 4096;        // [c][d] natural

    const int tid = threadIdx.x;
    const int ty = tid >> 4;      // row group: rows ty*4 .. ty*4+3
    const int tx = tid & 15;      // col group: cols tx*4 .. tx*4+3
    const int b  = blockIdx.z;
    const int h  = blockIdx.y;
    const int q0 = blockIdx.x * BQ;
    const size_t base = ((size_t)b * SEQ) * HIDD + (size_t)h * HD;
    const float scale = 0.125f;   // 1/sqrt(64)

    // Load Q tile, transposed + swizzled, pre-scaled
    for (int i = tid; i < BQ * 16; i += 256) {
        int r = i >> 4;
        int d = (i & 15) << 2;
        float4 qv = *(const float4*)(&g_Q[base + (size_t)(q0 + r) * HIDD + d]);
        Qt[swz(d + 0, r)] = qv.x * scale;
        Qt[swz(d + 1, r)] = qv.y * scale;
        Qt[swz(d + 2, r)] = qv.z * scale;
        Qt[swz(d + 3, r)] = qv.w * scale;
    }

    float acc[4][4], mrow[4], lrow[4];
#pragma unroll
    for (int i = 0; i < 4; i++) {
        mrow[i] = -1e30f;
        lrow[i] = 0.0f;
#pragma unroll
        for (int j = 0; j < 4; j++) acc[i][j] = 0.0f;
    }

    for (int k0 = 0; k0 < SEQ; k0 += BKV) {
        // Stage K (transposed swizzled) and V (natural)
        for (int i = tid; i < BKV * 16; i += 256) {
            int r = i >> 4;
            int d = (i & 15) << 2;
            size_t g = base + (size_t)(k0 + r) * HIDD + d;
            float4 kv = *(const float4*)(&g_K[g]);
            Kt[swz(d + 0, r)] = kv.x;
            Kt[swz(d + 1, r)] = kv.y;
            Kt[swz(d + 2, r)] = kv.z;
            Kt[swz(d + 3, r)] = kv.w;
            float4 vv = *(const float4*)(&g_V[g]);
            *(float4*)(&Vs[r * HD + d]) = vv;
        }
        __syncthreads();   // Qt (first iter) + Kt/Vs visible

        // Scores: s[i][j] = sum_d Qt[d][ty*4+i] * Kt[d][tx*4+j]  (Q pre-scaled)
        float s[4][4];
#pragma unroll
        for (int i = 0; i < 4; i++)
#pragma unroll
            for (int j = 0; j < 4; j++) s[i][j] = 0.0f;

#pragma unroll 8
        for (int d = 0; d < HD; d++) {
            float4 a4 = *(const float4*)(&Qt[swz(d, ty * 4)]);
            float4 b4 = *(const float4*)(&Kt[swz(d, tx * 4)]);
            float a[4] = {a4.x, a4.y, a4.z, a4.w};
            float bb[4] = {b4.x, b4.y, b4.z, b4.w};
#pragma unroll
            for (int i = 0; i < 4; i++)
#pragma unroll
                for (int j = 0; j < 4; j++)
                    s[i][j] = fmaf(a[i], bb[j], s[i][j]);
        }

        // Online softmax: row reductions across the 16 tx lanes (half-warp)
        float tmax[4], rsum[4];
#pragma unroll
        for (int i = 0; i < 4; i++)
            tmax[i] = fmaxf(fmaxf(s[i][0], s[i][1]), fmaxf(s[i][2], s[i][3]));
#pragma unroll
        for (int off = 8; off; off >>= 1)
#pragma unroll
            for (int i = 0; i < 4; i++)
                tmax[i] = fmaxf(tmax[i], __shfl_xor_sync(0xffffffffu, tmax[i], off));

#pragma unroll
        for (int i = 0; i < 4; i++) {
            float mnew = fmaxf(mrow[i], tmax[i]);
            float corr = __expf(mrow[i] - mnew);
            mrow[i] = mnew;
            float rs = 0.0f;
#pragma unroll
            for (int j = 0; j < 4; j++) {
                float p = __expf(s[i][j] - mnew);
                s[i][j] = p;
                rs += p;
            }
            rsum[i] = rs;
            lrow[i] *= corr;
#pragma unroll
            for (int j = 0; j < 4; j++) acc[i][j] *= corr;
        }
#pragma unroll
        for (int off = 8; off; off >>= 1)
#pragma unroll
            for (int i = 0; i < 4; i++)
                rsum[i] += __shfl_xor_sync(0xffffffffu, rsum[i], off);
#pragma unroll
        for (int i = 0; i < 4; i++) lrow[i] += rsum[i];

        // P -> shared (transposed swizzled: element (c, r))
#pragma unroll
        for (int j = 0; j < 4; j++)
#pragma unroll
            for (int i = 0; i < 4; i++)
                Pt[swz(tx * 4 + j, ty * 4 + i)] = s[i][j];
        __syncthreads();

        // O += P @ V  (outer product over keys c)
#pragma unroll 8
        for (int c = 0; c < BKV; c++) {
            float4 p4 = *(const float4*)(&Pt[swz(c, ty * 4)]);
            float4 v4 = *(const float4*)(&Vs[c * HD + tx * 4]);
            float p[4] = {p4.x, p4.y, p4.z, p4.w};
            float vv[4] = {v4.x, v4.y, v4.z, v4.w};
#pragma unroll
            for (int i = 0; i < 4; i++)
#pragma unroll
                for (int j = 0; j < 4; j++)
                    acc[i][j] = fmaf(p[i], vv[j], acc[i][j]);
        }
        __syncthreads();   // done with Kt/Vs/Pt before next stage
    }

    // Epilogue: normalize and write O[b, q, h*64 + d]
#pragma unroll
    for (int i = 0; i < 4; i++) {
        float inv = 1.0f / lrow[i];
        float4 o = make_float4(acc[i][0] * inv, acc[i][1] * inv,
                               acc[i][2] * inv, acc[i][3] * inv);
        *(float4*)(&g_O[base + (size_t)(q0 + ty * 4 + i) * HIDD + tx * 4]) = o;
    }
}

// ---------------------------------------------------------------------------
// Launch: 3 dependent kernels on the capture stream. No syncs, no allocs.
// ---------------------------------------------------------------------------
extern "C" void kernel_launch(void* const* d_in, const int* in_sizes, int n_in,
                              void* d_out, int out_size)
{
    const float* q  = (const float*)d_in[0];
    const float* k  = (const float*)d_in[1];
    const float* v  = (const float*)d_in[2];
    const float* Wq = (const float*)d_in[3];
    const float* Wk = (const float*)d_in[4];
    const float* Wv = (const float*)d_in[5];
    const float* Wo = (const float*)d_in[6];
    float* out = (float*)d_out;
    (void)in_sizes; (void)n_in; (void)out_size;

    // 64 KB dynamic SMEM for the flash kernel (host-side attribute set, not a
    // stream op — safe under graph capture; idempotent).
    cudaFuncSetAttribute(flash_kernel,
                         cudaFuncAttributeMaxDynamicSharedMemorySize, 65536);

    dim3 gproj(GN / BN, GM / BM, 3);            // 8 x 64 x 3
    qkv_gemm_kernel<<<gproj, 256>>>(q, k, v, Wq, Wk, Wv);

    dim3 gattn(SEQ / BQ, NH, BATCH);            // 32 x 16 x 4
    flash_kernel<<<gattn, 256, 65536>>>();

    dim3 gout(GN / BN, GM / BM);                // 8 x 64
    out_gemm_kernel<<<gout, 256>>>(Wo, out);
}

// round 6
// speedup vs baseline: 3.3317x; 3.3317x over previous
#include <cuda_runtime.h>
#include <math.h>
#include <stdint.h>

// Problem constants
#define BATCH 4
#define SEQ   2048
#define HIDD  1024
#define NH    16
#define HD    64

#define GM (BATCH*SEQ)
#define GK HIDD
#define GN HIDD

// Scratch (__device__ globals: allocations are forbidden)
__device__ float g_Q[BATCH*SEQ*HIDD];
__device__ float g_K[BATCH*SEQ*HIDD];
__device__ float g_V[BATCH*SEQ*HIDD];
__device__ float g_O[BATCH*SEQ*HIDD];

// ---------------------------------------------------------------------------
// tf32 helpers
// ---------------------------------------------------------------------------
__device__ __forceinline__ uint32_t f2tf(float x) {
    uint32_t y;
    asm("cvt.rna.tf32.f32 %0, %1;" : "=r"(y) : "f"(x));
    return y;
}
__device__ __forceinline__ float f2tff(float x) { return __uint_as_float(f2tf(x)); }

// D += A(m16k8,row) * B(k8n8,col), tf32 in, f32 accum
__device__ __forceinline__ void mma_tf32(float* d, const uint32_t* a, const uint32_t* b) {
    asm volatile(
        "mma.sync.aligned.m16n8k8.row.col.f32.tf32.tf32.f32 "
        "{%0,%1,%2,%3}, {%4,%5,%6,%7}, {%8,%9}, {%0,%1,%2,%3};"
        : "+f"(d[0]), "+f"(d[1]), "+f"(d[2]), "+f"(d[3])
        : "r"(a[0]), "r"(a[1]), "r"(a[2]), "r"(a[3]), "r"(b[0]), "r"(b[1]));
}

// ---------------------------------------------------------------------------
// TF32 tensor-core GEMM: C[M,N] = A[M,K] @ W[K,N]. 128x128x32 CTA tile,
// 8 warps (2x4), warp tile 64x32, m16n8k8 fragments.
// SMEM strides chosen for conflict-free fragment loads:
//   As stride 36: a-frag bank = (4g+tg)%32 -> all distinct
//   Bs stride 136: b-frag bank = (8tg+g)%32 -> all distinct
// ---------------------------------------------------------------------------
#define BM 128
#define BN 128
#define BK 32
#define ASTR 36
#define BSTR 136

__device__ __forceinline__ void gemm_body(const float* __restrict__ A,
                                          const float* __restrict__ W,
                                          float* __restrict__ C)
{
    __shared__ float As[BM * ASTR];
    __shared__ float Bs[BK * BSTR];

    const int tid  = threadIdx.x;
    const int w    = tid >> 5;
    const int lane = tid & 31;
    const int g    = lane >> 2;     // 0..7
    const int tg   = lane & 3;      // 0..3
    const int wm   = w >> 2;        // 0..1 -> 64 rows
    const int wn   = w & 3;         // 0..3 -> 32 cols
    const int bm   = blockIdx.y * BM;
    const int bn   = blockIdx.x * BN;

    float acc[4][4][4] = {};

    for (int k0 = 0; k0 < GK; k0 += BK) {
        // Stage A 128x32 (row-major, tf32-rounded)
#pragma unroll
        for (int t = 0; t < 4; t++) {
            int idx = t * 256 + tid;
            int r = idx >> 3, c = (idx & 7) << 2;
            float4 a4 = *(const float4*)(A + (size_t)(bm + r) * GK + k0 + c);
            *(float4*)(&As[r * ASTR + c]) =
                make_float4(f2tff(a4.x), f2tff(a4.y), f2tff(a4.z), f2tff(a4.w));
        }
        // Stage W 32x128
#pragma unroll
        for (int t = 0; t < 4; t++) {
            int idx = t * 256 + tid;
            int r = idx >> 5, c = (idx & 31) << 2;
            float4 b4 = *(const float4*)(W + (size_t)(k0 + r) * GN + bn + c);
            *(float4*)(&Bs[r * BSTR + c]) =
                make_float4(f2tff(b4.x), f2tff(b4.y), f2tff(b4.z), f2tff(b4.w));
        }
        __syncthreads();

#pragma unroll
        for (int kk = 0; kk < 4; kk++) {
            int kb = kk * 8;
            uint32_t af[4][4], bf[4][2];
#pragma unroll
            for (int mf = 0; mf < 4; mf++) {
                int r0 = wm * 64 + mf * 16 + g;
                af[mf][0] = __float_as_uint(As[(r0)     * ASTR + kb + tg]);
                af[mf][1] = __float_as_uint(As[(r0 + 8) * ASTR + kb + tg]);
                af[mf][2] = __float_as_uint(As[(r0)     * ASTR + kb + tg + 4]);
                af[mf][3] = __float_as_uint(As[(r0 + 8) * ASTR + kb + tg + 4]);
            }
#pragma unroll
            for (int nf = 0; nf < 4; nf++) {
                int c0 = wn * 32 + nf * 8 + g;
                bf[nf][0] = __float_as_uint(Bs[(kb + tg)     * BSTR + c0]);
                bf[nf][1] = __float_as_uint(Bs[(kb + tg + 4) * BSTR + c0]);
            }
#pragma unroll
            for (int mf = 0; mf < 4; mf++)
#pragma unroll
                for (int nf = 0; nf < 4; nf++)
                    mma_tf32(acc[mf][nf], af[mf], bf[nf]);
        }
        __syncthreads();
    }

    // Epilogue: c-layout (row g/g+8, cols 2tg,2tg+1) -> float2 stores
#pragma unroll
    for (int mf = 0; mf < 4; mf++) {
        int r0 = bm + wm * 64 + mf * 16 + g;
#pragma unroll
        for (int nf = 0; nf < 4; nf++) {
            int c0 = bn + wn * 32 + nf * 8 + 2 * tg;
            *(float2*)(C + (size_t)r0 * GN + c0) =
                make_float2(acc[mf][nf][0], acc[mf][nf][1]);
            *(float2*)(C + (size_t)(r0 + 8) * GN + c0) =
                make_float2(acc[mf][nf][2], acc[mf][nf][3]);
        }
    }
}

__global__ void __launch_bounds__(256, 2) qkv_gemm_kernel(
    const float* __restrict__ q, const float* __restrict__ k, const float* __restrict__ v,
    const float* __restrict__ Wq, const float* __restrict__ Wk, const float* __restrict__ Wv)
{
    const float* A; const float* W; float* C;
    if (blockIdx.z == 0)      { A = q; W = Wq; C = g_Q; }
    else if (blockIdx.z == 1) { A = k; W = Wk; C = g_K; }
    else                      { A = v; W = Wv; C = g_V; }
    gemm_body(A, W, C);
}

__global__ void __launch_bounds__(256, 2) out_gemm_kernel(
    const float* __restrict__ Wo, float* __restrict__ out)
{
    gemm_body(g_O, Wo, out);
}

// ---------------------------------------------------------------------------
// Flash attention, tensor-core edition.
// CTA = (b, h, 128-query tile), 8 warps; warp w owns FULL rows w*16..w*16+15
// (n = all 64 keys / all 64 d) -> softmax is warp-local (quad shuffles only).
// P stays in registers: C-layout -> A-layout via width-4 shuffles for PV.
// SMEM strides: Qs 68 (a-frag bank 4g+tg, distinct), Ks 68 (b-frag 4g+tg),
// Vs 72 (b-frag 8tg+g) -> all fragment loads conflict-free.
// ---------------------------------------------------------------------------
#define FQ   128
#define FKV  64
#define QSTR 68
#define KSTR 68
#define VSTR 72
#define FLASH_SMEM ((FQ*QSTR + FKV*KSTR + FKV*VSTR) * 4)   // 70656 bytes

__global__ void __launch_bounds__(256, 2) flash_kernel()
{
    extern __shared__ float sm[];
    float* Qs = sm;                    // [128][68] tf32, pre-scaled
    float* Ks = Qs + FQ * QSTR;        // [64][68] tf32
    float* Vs = Ks + FKV * KSTR;       // [64][72] tf32

    const int tid  = threadIdx.x;
    const int w    = tid >> 5;
    const int lane = tid & 31;
    const int g    = lane >> 2;
    const int tg   = lane & 3;
    const int b    = blockIdx.z;
    const int h    = blockIdx.y;
    const int q0   = blockIdx.x * FQ;
    const size_t base = ((size_t)b * SEQ) * HIDD + (size_t)h * HD;
    const float scale = 0.125f;        // 1/sqrt(64), folded into Q
    const int r0 = w * 16;

    // Load Q tile 128x64 (scaled, tf32-rounded)
#pragma unroll
    for (int t = 0; t < 8; t++) {
        int idx = t * 256 + tid;
        int r = idx >> 4, c = (idx & 15) << 2;
        float4 q4 = *(const float4*)(&g_Q[base + (size_t)(q0 + r) * HIDD + c]);
        *(float4*)(&Qs[r * QSTR + c]) = make_float4(
            f2tff(q4.x * scale), f2tff(q4.y * scale),
            f2tff(q4.z * scale), f2tff(q4.w * scale));
    }

    float o[8][4] = {};
    float m_lo = -1e30f, m_hi = -1e30f, l_lo = 0.0f, l_hi = 0.0f;

    for (int k0 = 0; k0 < SEQ; k0 += FKV) {
        __syncthreads();   // previous iter's PV reads of Ks/Vs done
        // Stage K, V 64x64 each
#pragma unroll
        for (int t = 0; t < 4; t++) {
            int idx = t * 256 + tid;
            int r = idx >> 4, c = (idx & 15) << 2;
            size_t gp = base + (size_t)(k0 + r) * HIDD + c;
            float4 k4 = *(const float4*)(&g_K[gp]);
            *(float4*)(&Ks[r * KSTR + c]) =
                make_float4(f2tff(k4.x), f2tff(k4.y), f2tff(k4.z), f2tff(k4.w));
            float4 v4 = *(const float4*)(&g_V[gp]);
            *(float4*)(&Vs[r * VSTR + c]) =
                make_float4(f2tff(v4.x), f2tff(v4.y), f2tff(v4.z), f2tff(v4.w));
        }
        __syncthreads();

        // ---- S = Q @ K^T : warp computes 16x64, k=64 ----
        float s[8][4] = {};
#pragma unroll
        for (int kk = 0; kk < 8; kk++) {
            int kb = kk * 8;
            uint32_t af[4];
            af[0] = __float_as_uint(Qs[(r0 + g)     * QSTR + kb + tg]);
            af[1] = __float_as_uint(Qs[(r0 + g + 8) * QSTR + kb + tg]);
            af[2] = __float_as_uint(Qs[(r0 + g)     * QSTR + kb + tg + 4]);
            af[3] = __float_as_uint(Qs[(r0 + g + 8) * QSTR + kb + tg + 4]);
#pragma unroll
            for (int nf = 0; nf < 8; nf++) {
                int n = nf * 8 + g;
                uint32_t bf[2];
                bf[0] = __float_as_uint(Ks[n * KSTR + kb + tg]);
                bf[1] = __float_as_uint(Ks[n * KSTR + kb + tg + 4]);
                mma_tf32(s[nf], af, bf);
            }
        }

        // ---- online softmax (warp-local: quad shuffles over tg) ----
        float tm_lo = -1e30f, tm_hi = -1e30f;
#pragma unroll
        for (int nf = 0; nf < 8; nf++) {
            tm_lo = fmaxf(tm_lo, fmaxf(s[nf][0], s[nf][1]));
            tm_hi = fmaxf(tm_hi, fmaxf(s[nf][2], s[nf][3]));
        }
        tm_lo = fmaxf(tm_lo, __shfl_xor_sync(0xffffffffu, tm_lo, 1));
        tm_lo = fmaxf(tm_lo, __shfl_xor_sync(0xffffffffu, tm_lo, 2));
        tm_hi = fmaxf(tm_hi, __shfl_xor_sync(0xffffffffu, tm_hi, 1));
        tm_hi = fmaxf(tm_hi, __shfl_xor_sync(0xffffffffu, tm_hi, 2));

        float mn_lo = fmaxf(m_lo, tm_lo);
        float mn_hi = fmaxf(m_hi, tm_hi);
        float corr_lo = __expf(m_lo - mn_lo);
        float corr_hi = __expf(m_hi - mn_hi);
        m_lo = mn_lo; m_hi = mn_hi;

        float sum_lo = 0.0f, sum_hi = 0.0f;
#pragma unroll
        for (int nf = 0; nf < 8; nf++) {
            s[nf][0] = __expf(s[nf][0] - m_lo);
            s[nf][1] = __expf(s[nf][1] - m_lo);
            s[nf][2] = __expf(s[nf][2] - m_hi);
            s[nf][3] = __expf(s[nf][3] - m_hi);
            sum_lo += s[nf][0] + s[nf][1];
            sum_hi += s[nf][2] + s[nf][3];
        }
        sum_lo += __shfl_xor_sync(0xffffffffu, sum_lo, 1);
        sum_lo += __shfl_xor_sync(0xffffffffu, sum_lo, 2);
        sum_hi += __shfl_xor_sync(0xffffffffu, sum_hi, 1);
        sum_hi += __shfl_xor_sync(0xffffffffu, sum_hi, 2);
        l_lo = l_lo * corr_lo + sum_lo;
        l_hi = l_hi * corr_hi + sum_hi;

#pragma unroll
        for (int nf = 0; nf < 8; nf++) {
            o[nf][0] *= corr_lo;  o[nf][1] *= corr_lo;
            o[nf][2] *= corr_hi;  o[nf][3] *= corr_hi;
            // P -> tf32 for the PV mma
            s[nf][0] = f2tff(s[nf][0]);
            s[nf][1] = f2tff(s[nf][1]);
            s[nf][2] = f2tff(s[nf][2]);
            s[nf][3] = f2tff(s[nf][3]);
        }

        // ---- O += P @ V : P C-layout -> A-layout via width-4 shuffles ----
#pragma unroll
        for (int kc = 0; kc < 8; kc++) {
            int src1 = tg >> 1, src2 = src1 + 2;
            bool odd = (tg & 1);
            float e, d2;
            uint32_t af[4];
            e  = __shfl_sync(0xffffffffu, s[kc][0], src1, 4);
            d2 = __shfl_sync(0xffffffffu, s[kc][1], src1, 4);
            af[0] = __float_as_uint(odd ? d2 : e);
            e  = __shfl_sync(0xffffffffu, s[kc][2], src1, 4);
            d2 = __shfl_sync(0xffffffffu, s[kc][3], src1, 4);
            af[1] = __float_as_uint(odd ? d2 : e);
            e  = __shfl_sync(0xffffffffu, s[kc][0], src2, 4);
            d2 = __shfl_sync(0xffffffffu, s[kc][1], src2, 4);
            af[2] = __float_as_uint(odd ? d2 : e);
            e  = __shfl_sync(0xffffffffu, s[kc][2], src2, 4);
            d2 = __shfl_sync(0xffffffffu, s[kc][3], src2, 4);
            af[3] = __float_as_uint(odd ? d2 : e);

            int kb = kc * 8;
#pragma unroll
            for (int nf = 0; nf < 8; nf++) {
                int c0 = nf * 8 + g;
                uint32_t bf[2];
                bf[0] = __float_as_uint(Vs[(kb + tg)     * VSTR + c0]);
                bf[1] = __float_as_uint(Vs[(kb + tg + 4) * VSTR + c0]);
                mma_tf32(o[nf], af, bf);
            }
        }
    }

    // Epilogue: normalize, write O[b, q, h*64 + d]
    float inv_lo = 1.0f / l_lo;
    float inv_hi = 1.0f / l_hi;
#pragma unroll
    for (int nf = 0; nf < 8; nf++) {
        int col = nf * 8 + 2 * tg;
        size_t row = (size_t)(q0 + r0 + g);
        *(float2*)(&g_O[base + row * HIDD + col]) =
            make_float2(o[nf][0] * inv_lo, o[nf][1] * inv_lo);
        *(float2*)(&g_O[base + (row + 8) * HIDD + col]) =
            make_float2(o[nf][2] * inv_hi, o[nf][3] * inv_hi);
    }
}

// ---------------------------------------------------------------------------
// Launch: 3 dependent kernels, graph-capturable, allocation-free.
// ---------------------------------------------------------------------------
extern "C" void kernel_launch(void* const* d_in, const int* in_sizes, int n_in,
                              void* d_out, int out_size)
{
    const float* q  = (const float*)d_in[0];
    const float* k  = (const float*)d_in[1];
    const float* v  = (const float*)d_in[2];
    const float* Wq = (const float*)d_in[3];
    const float* Wk = (const float*)d_in[4];
    const float* Wv = (const float*)d_in[5];
    const float* Wo = (const float*)d_in[6];
    float* out = (float*)d_out;
    (void)in_sizes; (void)n_in; (void)out_size;

    cudaFuncSetAttribute(flash_kernel,
                         cudaFuncAttributeMaxDynamicSharedMemorySize, FLASH_SMEM);

    dim3 gproj(GN / BN, GM / BM, 3);            // 8 x 64 x 3
    qkv_gemm_kernel<<<gproj, 256>>>(q, k, v, Wq, Wk, Wv);

    dim3 gattn(SEQ / FQ, NH, BATCH);            // 16 x 16 x 4
    flash_kernel<<<gattn, 256, FLASH_SMEM>>>();

    dim3 gout(GN / BN, GM / BM);                // 8 x 64
    out_gemm_kernel<<<gout, 256>>>(Wo, out);
}

// round 9
// speedup vs baseline: 3.3559x; 1.0073x over previous
#include <cuda_runtime.h>
#include <math.h>
#include <stdint.h>

// Problem constants
#define BATCH 4
#define SEQ   2048
#define HIDD  1024
#define NH    16
#define HD    64

#define GM (BATCH*SEQ)
#define GK HIDD
#define GN HIDD

// Scratch (__device__ globals: allocations are forbidden)
__device__ float g_Q[BATCH*SEQ*HIDD];
__device__ float g_K[BATCH*SEQ*HIDD];
__device__ float g_V[BATCH*SEQ*HIDD];
__device__ float g_O[BATCH*SEQ*HIDD];

// ---------------------------------------------------------------------------
// tf32 helpers
// ---------------------------------------------------------------------------
__device__ __forceinline__ uint32_t f2tf(float x) {
    uint32_t y;
    asm("cvt.rna.tf32.f32 %0, %1;" : "=r"(y) : "f"(x));
    return y;
}
__device__ __forceinline__ float f2tff(float x) { return __uint_as_float(f2tf(x)); }
__device__ __forceinline__ float4 cvt4(float4 a) {
    return make_float4(f2tff(a.x), f2tff(a.y), f2tff(a.z), f2tff(a.w));
}

// D += A(m16k8,row) * B(k8n8,col), tf32 in, f32 accum
__device__ __forceinline__ void mma_tf32(float* d, const uint32_t* a, const uint32_t* b) {
    asm volatile(
        "mma.sync.aligned.m16n8k8.row.col.f32.tf32.tf32.f32 "
        "{%0,%1,%2,%3}, {%4,%5,%6,%7}, {%8,%9}, {%0,%1,%2,%3};"
        : "+f"(d[0]), "+f"(d[1]), "+f"(d[2]), "+f"(d[3])
        : "r"(a[0]), "r"(a[1]), "r"(a[2]), "r"(a[3]), "r"(b[0]), "r"(b[1]));
}

// ---------------------------------------------------------------------------
// TF32 GEMM: C[M,N] = A[M,K] @ W[K,N].
// CTA 128x128, 4 warps (2x2), warp tile 64x64 (4mf x 8nf), TK=16,
// double-buffered smem with reg prefetch: one __syncthreads per k-iter.
// ASTR=20: a-frag bank = (4g+tg) distinct. BSTR=136: b-frag bank = (8tg+g).
// ---------------------------------------------------------------------------
#define TK   16
#define ASTR 20
#define BSTR 136

__device__ __forceinline__ void gemm_body(const float* __restrict__ A,
                                          const float* __restrict__ W,
                                          float* __restrict__ C)
{
    __shared__ float As[2][128 * ASTR];
    __shared__ float Bs[2][TK * BSTR];

    const int tid  = threadIdx.x;
    const int w    = tid >> 5;
    const int lane = tid & 31;
    const int g    = lane >> 2;
    const int tg   = lane & 3;
    const int wm   = w >> 1;        // 0..1 -> 64 rows
    const int wn   = w & 1;         // 0..1 -> 64 cols
    const int bm   = blockIdx.y * 128;
    const int bn   = blockIdx.x * 128;

    float acc[4][8][4] = {};
    float4 pa[4], pb[4];

    // ---- prefetch tile 0 ----
#pragma unroll
    for (int t = 0; t < 4; t++) {
        int idx = t * 128 + tid;
        int r = idx >> 2, c = (idx & 3) << 2;
        pa[t] = *(const float4*)(A + (size_t)(bm + r) * GK + c);
    }
#pragma unroll
    for (int t = 0; t < 4; t++) {
        int idx = t * 128 + tid;
        int r = idx >> 5, c = (idx & 31) << 2;
        pb[t] = *(const float4*)(W + (size_t)r * GN + bn + c);
    }
#pragma unroll
    for (int t = 0; t < 4; t++) {
        int idx = t * 128 + tid;
        int r = idx >> 2, c = (idx & 3) << 2;
        *(float4*)(&As[0][r * ASTR + c]) = cvt4(pa[t]);
    }
#pragma unroll
    for (int t = 0; t < 4; t++) {
        int idx = t * 128 + tid;
        int r = idx >> 5, c = (idx & 31) << 2;
        *(float4*)(&Bs[0][r * BSTR + c]) = cvt4(pb[t]);
    }
    __syncthreads();

    const int NIT = GK / TK;        // 64
    for (int it = 0; it < NIT; it++) {
        const int cur = it & 1;
        // prefetch next tile into regs (latency hidden behind compute)
        if (it + 1 < NIT) {
            int k0 = (it + 1) * TK;
#pragma unroll
            for (int t = 0; t < 4; t++) {
                int idx = t * 128 + tid;
                int r = idx >> 2, c = (idx & 3) << 2;
                pa[t] = *(const float4*)(A + (size_t)(bm + r) * GK + k0 + c);
            }
#pragma unroll
            for (int t = 0; t < 4; t++) {
                int idx = t * 128 + tid;
                int r = idx >> 5, c = (idx & 31) << 2;
                pb[t] = *(const float4*)(W + (size_t)(k0 + r) * GN + bn + c);
            }
        }

        // compute current tile
#pragma unroll
        for (int kk = 0; kk < 2; kk++) {
            int kb = kk * 8;
            uint32_t af[4][4], bf[8][2];
#pragma unroll
            for (int mf = 0; mf < 4; mf++) {
                int r0 = wm * 64 + mf * 16 + g;
                af[mf][0] = __float_as_uint(As[cur][(r0)     * ASTR + kb + tg]);
                af[mf][1] = __float_as_uint(As[cur][(r0 + 8) * ASTR + kb + tg]);
                af[mf][2] = __float_as_uint(As[cur][(r0)     * ASTR + kb + tg + 4]);
                af[mf][3] = __float_as_uint(As[cur][(r0 + 8) * ASTR + kb + tg + 4]);
            }
#pragma unroll
            for (int nf = 0; nf < 8; nf++) {
                int c0 = wn * 64 + nf * 8 + g;
                bf[nf][0] = __float_as_uint(Bs[cur][(kb + tg)     * BSTR + c0]);
                bf[nf][1] = __float_as_uint(Bs[cur][(kb + tg + 4) * BSTR + c0]);
            }
#pragma unroll
            for (int mf = 0; mf < 4; mf++)
#pragma unroll
                for (int nf = 0; nf < 8; nf++)
                    mma_tf32(acc[mf][nf], af[mf], bf[nf]);
        }

        // stage prefetched tile into the other buffer
        if (it + 1 < NIT) {
            int nxt = cur ^ 1;
#pragma unroll
            for (int t = 0; t < 4; t++) {
                int idx = t * 128 + tid;
                int r = idx >> 2, c = (idx & 3) << 2;
                *(float4*)(&As[nxt][r * ASTR + c]) = cvt4(pa[t]);
            }
#pragma unroll
            for (int t = 0; t < 4; t++) {
                int idx = t * 128 + tid;
                int r = idx >> 5, c = (idx & 31) << 2;
                *(float4*)(&Bs[nxt][r * BSTR + c]) = cvt4(pb[t]);
            }
        }
        __syncthreads();
    }

    // Epilogue: c-layout float2 stores
#pragma unroll
    for (int mf = 0; mf < 4; mf++) {
        int r0 = bm + wm * 64 + mf * 16 + g;
#pragma unroll
        for (int nf = 0; nf < 8; nf++) {
            int c0 = bn + wn * 64 + nf * 8 + 2 * tg;
            *(float2*)(C + (size_t)r0 * GN + c0) =
                make_float2(acc[mf][nf][0], acc[mf][nf][1]);
            *(float2*)(C + (size_t)(r0 + 8) * GN + c0) =
                make_float2(acc[mf][nf][2], acc[mf][nf][3]);
        }
    }
}

__global__ void __launch_bounds__(128) qkv_gemm_kernel(
    const float* __restrict__ q, const float* __restrict__ k, const float* __restrict__ v,
    const float* __restrict__ Wq, const float* __restrict__ Wk, const float* __restrict__ Wv)
{
    const float* A; const float* W; float* C;
    if (blockIdx.z == 0)      { A = q; W = Wq; C = g_Q; }
    else if (blockIdx.z == 1) { A = k; W = Wk; C = g_K; }
    else                      { A = v; W = Wv; C = g_V; }
    gemm_body(A, W, C);
}

__global__ void __launch_bounds__(128) out_gemm_kernel(
    const float* __restrict__ Wo, float* __restrict__ out)
{
    gemm_body(g_O, Wo, out);
}

// ---------------------------------------------------------------------------
// Flash attention: CTA = (b, h, 128-query tile), 4 warps.
// Warp w owns rows w*32..w*32+31 (2 row-frags), all 64 keys -> warp-local
// softmax. Q a-frags hoisted to registers for the whole kernel (staged once
// through the K buffer); K/V frags loaded once per (k,n) and reused for both
// row-frags. KSTR=68 / VSTR=72 keep all frag loads conflict-free.
// ---------------------------------------------------------------------------
#define FKV  64
#define KSTR 68
#define VSTR 72

__global__ void __launch_bounds__(128) flash_kernel()
{
    __shared__ float Ks[FKV * KSTR];   // also used to stage Q at start
    __shared__ float Vs[FKV * VSTR];

    const int tid  = threadIdx.x;
    const int w    = tid >> 5;
    const int lane = tid & 31;
    const int g    = lane >> 2;
    const int tg   = lane & 3;
    const int b    = blockIdx.z;
    const int h    = blockIdx.y;
    const int q0   = blockIdx.x * 128;
    const size_t base = ((size_t)b * SEQ) * HIDD + (size_t)h * HD;

    // ---- hoist Q fragments into registers (two 64-row staging passes) ----
    uint32_t qf[8][2][4];
#pragma unroll
    for (int ch = 0; ch < 2; ch++) {
#pragma unroll
        for (int t = 0; t < 8; t++) {
            int idx = t * 128 + tid;
            int r = idx >> 4, c = (idx & 15) << 2;
            float4 q4 = *(const float4*)(&g_Q[base + (size_t)(q0 + ch * 64 + r) * HIDD + c]);
            *(float4*)(&Ks[r * KSTR + c]) = make_float4(
                f2tff(q4.x * 0.125f), f2tff(q4.y * 0.125f),
                f2tff(q4.z * 0.125f), f2tff(q4.w * 0.125f));
        }
        __syncthreads();
        if ((w >> 1) == ch) {
            int lr = (w & 1) * 32;
#pragma unroll
            for (int kk = 0; kk < 8; kk++) {
                int kb = kk * 8;
#pragma unroll
                for (int mf = 0; mf < 2; mf++) {
                    int r0 = lr + mf * 16 + g;
                    qf[kk][mf][0] = __float_as_uint(Ks[(r0)     * KSTR + kb + tg]);
                    qf[kk][mf][1] = __float_as_uint(Ks[(r0 + 8) * KSTR + kb + tg]);
                    qf[kk][mf][2] = __float_as_uint(Ks[(r0)     * KSTR + kb + tg + 4]);
                    qf[kk][mf][3] = __float_as_uint(Ks[(r0 + 8) * KSTR + kb + tg + 4]);
                }
            }
        }
        __syncthreads();
    }

    float o[2][8][4] = {};
    float m[2][2] = {{-1e30f, -1e30f}, {-1e30f, -1e30f}};
    float l[2][2] = {{0.0f, 0.0f}, {0.0f, 0.0f}};

    for (int k0 = 0; k0 < SEQ; k0 += FKV) {
        __syncthreads();   // previous iter's reads of Ks/Vs complete
        // stage K, V (64x64 each)
#pragma unroll
        for (int t = 0; t < 8; t++) {
            int idx = t * 128 + tid;
            int r = idx >> 4, c = (idx & 15) << 2;
            size_t gp = base + (size_t)(k0 + r) * HIDD + c;
            float4 k4 = *(const float4*)(&g_K[gp]);
            *(float4*)(&Ks[r * KSTR + c]) = cvt4(k4);
            float4 v4 = *(const float4*)(&g_V[gp]);
            *(float4*)(&Vs[r * VSTR + c]) = cvt4(v4);
        }
        __syncthreads();

        // ---- S = Q @ K^T : 32 rows x 64 keys per warp ----
        float s[2][8][4] = {};
#pragma unroll
        for (int kk = 0; kk < 8; kk++) {
            int kb = kk * 8;
#pragma unroll
            for (int nf = 0; nf < 8; nf++) {
                int n = nf * 8 + g;
                uint32_t bf[2];
                bf[0] = __float_as_uint(Ks[n * KSTR + kb + tg]);
                bf[1] = __float_as_uint(Ks[n * KSTR + kb + tg + 4]);
                mma_tf32(s[0][nf], qf[kk][0], bf);
                mma_tf32(s[1][nf], qf[kk][1], bf);
            }
        }

        // ---- online softmax per row-frag (warp-local quad shuffles) ----
#pragma unroll
        for (int mf = 0; mf < 2; mf++) {
            float tlo = -1e30f, thi = -1e30f;
#pragma unroll
            for (int nf = 0; nf < 8; nf++) {
                tlo = fmaxf(tlo, fmaxf(s[mf][nf][0], s[mf][nf][1]));
                thi = fmaxf(thi, fmaxf(s[mf][nf][2], s[mf][nf][3]));
            }
            tlo = fmaxf(tlo, __shfl_xor_sync(0xffffffffu, tlo, 1));
            tlo = fmaxf(tlo, __shfl_xor_sync(0xffffffffu, tlo, 2));
            thi = fmaxf(thi, __shfl_xor_sync(0xffffffffu, thi, 1));
            thi = fmaxf(thi, __shfl_xor_sync(0xffffffffu, thi, 2));

            float mn_lo = fmaxf(m[mf][0], tlo);
            float mn_hi = fmaxf(m[mf][1], thi);
            float corr_lo = __expf(m[mf][0] - mn_lo);
            float corr_hi = __expf(m[mf][1] - mn_hi);
            m[mf][0] = mn_lo; m[mf][1] = mn_hi;

            float sum_lo = 0.0f, sum_hi = 0.0f;
#pragma unroll
            for (int nf = 0; nf < 8; nf++) {
                s[mf][nf][0] = __expf(s[mf][nf][0] - mn_lo);
                s[mf][nf][1] = __expf(s[mf][nf][1] - mn_lo);
                s[mf][nf][2] = __expf(s[mf][nf][2] - mn_hi);
                s[mf][nf][3] = __expf(s[mf][nf][3] - mn_hi);
                sum_lo += s[mf][nf][0] + s[mf][nf][1];
                sum_hi += s[mf][nf][2] + s[mf][nf][3];
            }
            sum_lo += __shfl_xor_sync(0xffffffffu, sum_lo, 1);
            sum_lo += __shfl_xor_sync(0xffffffffu, sum_lo, 2);
            sum_hi += __shfl_xor_sync(0xffffffffu, sum_hi, 1);
            sum_hi += __shfl_xor_sync(0xffffffffu, sum_hi, 2);
            l[mf][0] = l[mf][0] * corr_lo + sum_lo;
            l[mf][1] = l[mf][1] * corr_hi + sum_hi;

#pragma unroll
            for (int nf = 0; nf < 8; nf++) {
                o[mf][nf][0] *= corr_lo;  o[mf][nf][1] *= corr_lo;
                o[mf][nf][2] *= corr_hi;  o[mf][nf][3] *= corr_hi;
                s[mf][nf][0] = f2tff(s[mf][nf][0]);
                s[mf][nf][1] = f2tff(s[mf][nf][1]);
                s[mf][nf][2] = f2tff(s[mf][nf][2]);
                s[mf][nf][3] = f2tff(s[mf][nf][3]);
            }
        }

        // ---- O += P @ V : C-layout -> A-layout via width-4 shuffles ----
#pragma unroll
        for (int kc = 0; kc < 8; kc++) {
            int kb = kc * 8;
            int src1 = tg >> 1, src2 = src1 + 2;
            bool odd = (tg & 1);
            uint32_t af[2][4];
#pragma unroll
            for (int mf = 0; mf < 2; mf++) {
                float e, d2;
                e  = __shfl_sync(0xffffffffu, s[mf][kc][0], src1, 4);
                d2 = __shfl_sync(0xffffffffu, s[mf][kc][1], src1, 4);
                af[mf][0] = __float_as_uint(odd ? d2 : e);
                e  = __shfl_sync(0xffffffffu, s[mf][kc][2], src1, 4);
                d2 = __shfl_sync(0xffffffffu, s[mf][kc][3], src1, 4);
                af[mf][1] = __float_as_uint(odd ? d2 : e);
                e  = __shfl_sync(0xffffffffu, s[mf][kc][0], src2, 4);
                d2 = __shfl_sync(0xffffffffu, s[mf][kc][1], src2, 4);
                af[mf][2] = __float_as_uint(odd ? d2 : e);
                e  = __shfl_sync(0xffffffffu, s[mf][kc][2], src2, 4);
                d2 = __shfl_sync(0xffffffffu, s[mf][kc][3], src2, 4);
                af[mf][3] = __float_as_uint(odd ? d2 : e);
            }
#pragma unroll
            for (int nf = 0; nf < 8; nf++) {
                int c0 = nf * 8 + g;
                uint32_t bf[2];
                bf[0] = __float_as_uint(Vs[(kb + tg)     * VSTR + c0]);
                bf[1] = __float_as_uint(Vs[(kb + tg + 4) * VSTR + c0]);
                mma_tf32(o[0][nf], af[0], bf);
                mma_tf32(o[1][nf], af[1], bf);
            }
        }
    }

    // ---- epilogue: normalize + write O ----
#pragma unroll
    for (int mf = 0; mf < 2; mf++) {
        float inv0 = 1.0f / l[mf][0];
        float inv1 = 1.0f / l[mf][1];
        size_t row = (size_t)(q0 + w * 32 + mf * 16 + g);
#pragma unroll
        for (int nf = 0; nf < 8; nf++) {
            int col = nf * 8 + 2 * tg;
            *(float2*)(&g_O[base + row * HIDD + col]) =
                make_float2(o[mf][nf][0] * inv0, o[mf][nf][1] * inv0);
            *(float2*)(&g_O[base + (row + 8) * HIDD + col]) =
                make_float2(o[mf][nf][2] * inv1, o[mf][nf][3] * inv1);
        }
    }
}

// ---------------------------------------------------------------------------
// Launch: 3 dependent kernels, graph-capturable, allocation-free.
// ---------------------------------------------------------------------------
extern "C" void kernel_launch(void* const* d_in, const int* in_sizes, int n_in,
                              void* d_out, int out_size)
{
    const float* q  = (const float*)d_in[0];
    const float* k  = (const float*)d_in[1];
    const float* v  = (const float*)d_in[2];
    const float* Wq = (const float*)d_in[3];
    const float* Wk = (const float*)d_in[4];
    const float* Wv = (const float*)d_in[5];
    const float* Wo = (const float*)d_in[6];
    float* out = (float*)d_out;
    (void)in_sizes; (void)n_in; (void)out_size;

    dim3 gproj(GN / 128, GM / 128, 3);          // 8 x 64 x 3
    qkv_gemm_kernel<<<gproj, 128>>>(q, k, v, Wq, Wk, Wv);

    dim3 gattn(SEQ / 128, NH, BATCH);           // 16 x 16 x 4
    flash_kernel<<<gattn, 128>>>();

    dim3 gout(GN / 128, GM / 128);              // 8 x 64
    out_gemm_kernel<<<gout, 128>>>(Wo, out);
}

// round 10
// speedup vs baseline: 3.3567x; 1.0002x over previous
#include <cuda_runtime.h>
#include <math.h>
#include <stdint.h>

// Problem constants
#define BATCH 4
#define SEQ   2048
#define HIDD  1024
#define NH    16
#define HD    64

#define GM (BATCH*SEQ)
#define GK HIDD
#define GN HIDD

// Scratch (__device__ globals: allocations are forbidden)
__device__ float g_Q[BATCH*SEQ*HIDD];
__device__ float g_K[BATCH*SEQ*HIDD];
__device__ float g_V[BATCH*SEQ*HIDD];
__device__ float g_O[BATCH*SEQ*HIDD];

// ---------------------------------------------------------------------------
// tf32 helpers
// ---------------------------------------------------------------------------
__device__ __forceinline__ uint32_t f2tf(float x) {
    uint32_t y;
    asm("cvt.rna.tf32.f32 %0, %1;" : "=r"(y) : "f"(x));
    return y;
}
__device__ __forceinline__ float f2tff(float x) { return __uint_as_float(f2tf(x)); }
__device__ __forceinline__ float4 cvt4(float4 a) {
    return make_float4(f2tff(a.x), f2tff(a.y), f2tff(a.z), f2tff(a.w));
}

// D += A(m16k8,row) * B(k8n8,col), tf32 in, f32 accum
__device__ __forceinline__ void mma_tf32(float* d, const uint32_t* a, const uint32_t* b) {
    asm volatile(
        "mma.sync.aligned.m16n8k8.row.col.f32.tf32.tf32.f32 "
        "{%0,%1,%2,%3}, {%4,%5,%6,%7}, {%8,%9}, {%0,%1,%2,%3};"
        : "+f"(d[0]), "+f"(d[1]), "+f"(d[2]), "+f"(d[3])
        : "r"(a[0]), "r"(a[1]), "r"(a[2]), "r"(a[3]), "r"(b[0]), "r"(b[1]));
}

// ---------------------------------------------------------------------------
// TF32 GEMM: C[M,N] = A[M,K] @ W[K,N].
// CTA 128x128, 4 warps (2x2), warp tile 64x64 (4mf x 8nf), TK=16,
// double-buffered smem with reg prefetch: one __syncthreads per k-iter.
// ASTR=20: a-frag bank = (4g+tg) distinct. BSTR=136: b-frag bank = (8tg+g).
// ---------------------------------------------------------------------------
#define TK   16
#define ASTR 20
#define BSTR 136

__device__ __forceinline__ void gemm_body(const float* __restrict__ A,
                                          const float* __restrict__ W,
                                          float* __restrict__ C)
{
    __shared__ float As[2][128 * ASTR];
    __shared__ float Bs[2][TK * BSTR];

    const int tid  = threadIdx.x;
    const int w    = tid >> 5;
    const int lane = tid & 31;
    const int g    = lane >> 2;
    const int tg   = lane & 3;
    const int wm   = w >> 1;        // 0..1 -> 64 rows
    const int wn   = w & 1;         // 0..1 -> 64 cols
    const int bm   = blockIdx.y * 128;
    const int bn   = blockIdx.x * 128;

    float acc[4][8][4] = {};
    float4 pa[4], pb[4];

    // ---- prefetch tile 0 ----
#pragma unroll
    for (int t = 0; t < 4; t++) {
        int idx = t * 128 + tid;
        int r = idx >> 2, c = (idx & 3) << 2;
        pa[t] = *(const float4*)(A + (size_t)(bm + r) * GK + c);
    }
#pragma unroll
    for (int t = 0; t < 4; t++) {
        int idx = t * 128 + tid;
        int r = idx >> 5, c = (idx & 31) << 2;
        pb[t] = *(const float4*)(W + (size_t)r * GN + bn + c);
    }
#pragma unroll
    for (int t = 0; t < 4; t++) {
        int idx = t * 128 + tid;
        int r = idx >> 2, c = (idx & 3) << 2;
        *(float4*)(&As[0][r * ASTR + c]) = cvt4(pa[t]);
    }
#pragma unroll
    for (int t = 0; t < 4; t++) {
        int idx = t * 128 + tid;
        int r = idx >> 5, c = (idx & 31) << 2;
        *(float4*)(&Bs[0][r * BSTR + c]) = cvt4(pb[t]);
    }
    __syncthreads();

    const int NIT = GK / TK;        // 64
    for (int it = 0; it < NIT; it++) {
        const int cur = it & 1;
        // prefetch next tile into regs (latency hidden behind compute)
        if (it + 1 < NIT) {
            int k0 = (it + 1) * TK;
#pragma unroll
            for (int t = 0; t < 4; t++) {
                int idx = t * 128 + tid;
                int r = idx >> 2, c = (idx & 3) << 2;
                pa[t] = *(const float4*)(A + (size_t)(bm + r) * GK + k0 + c);
            }
#pragma unroll
            for (int t = 0; t < 4; t++) {
                int idx = t * 128 + tid;
                int r = idx >> 5, c = (idx & 31) << 2;
                pb[t] = *(const float4*)(W + (size_t)(k0 + r) * GN + bn + c);
            }
        }

        // compute current tile
#pragma unroll
        for (int kk = 0; kk < 2; kk++) {
            int kb = kk * 8;
            uint32_t af[4][4], bf[8][2];
#pragma unroll
            for (int mf = 0; mf < 4; mf++) {
                int r0 = wm * 64 + mf * 16 + g;
                af[mf][0] = __float_as_uint(As[cur][(r0)     * ASTR + kb + tg]);
                af[mf][1] = __float_as_uint(As[cur][(r0 + 8) * ASTR + kb + tg]);
                af[mf][2] = __float_as_uint(As[cur][(r0)     * ASTR + kb + tg + 4]);
                af[mf][3] = __float_as_uint(As[cur][(r0 + 8) * ASTR + kb + tg + 4]);
            }
#pragma unroll
            for (int nf = 0; nf < 8; nf++) {
                int c0 = wn * 64 + nf * 8 + g;
                bf[nf][0] = __float_as_uint(Bs[cur][(kb + tg)     * BSTR + c0]);
                bf[nf][1] = __float_as_uint(Bs[cur][(kb + tg + 4) * BSTR + c0]);
            }
#pragma unroll
            for (int mf = 0; mf < 4; mf++)
#pragma unroll
                for (int nf = 0; nf < 8; nf++)
                    mma_tf32(acc[mf][nf], af[mf], bf[nf]);
        }

        // stage prefetched tile into the other buffer
        if (it + 1 < NIT) {
            int nxt = cur ^ 1;
#pragma unroll
            for (int t = 0; t < 4; t++) {
                int idx = t * 128 + tid;
                int r = idx >> 2, c = (idx & 3) << 2;
                *(float4*)(&As[nxt][r * ASTR + c]) = cvt4(pa[t]);
            }
#pragma unroll
            for (int t = 0; t < 4; t++) {
                int idx = t * 128 + tid;
                int r = idx >> 5, c = (idx & 31) << 2;
                *(float4*)(&Bs[nxt][r * BSTR + c]) = cvt4(pb[t]);
            }
        }
        __syncthreads();
    }

    // Epilogue: c-layout float2 stores
#pragma unroll
    for (int mf = 0; mf < 4; mf++) {
        int r0 = bm + wm * 64 + mf * 16 + g;
#pragma unroll
        for (int nf = 0; nf < 8; nf++) {
            int c0 = bn + wn * 64 + nf * 8 + 2 * tg;
            *(float2*)(C + (size_t)r0 * GN + c0) =
                make_float2(acc[mf][nf][0], acc[mf][nf][1]);
            *(float2*)(C + (size_t)(r0 + 8) * GN + c0) =
                make_float2(acc[mf][nf][2], acc[mf][nf][3]);
        }
    }
}

__global__ void __launch_bounds__(128) qkv_gemm_kernel(
    const float* __restrict__ q, const float* __restrict__ k, const float* __restrict__ v,
    const float* __restrict__ Wq, const float* __restrict__ Wk, const float* __restrict__ Wv)
{
    const float* A; const float* W; float* C;
    if (blockIdx.z == 0)      { A = q; W = Wq; C = g_Q; }
    else if (blockIdx.z == 1) { A = k; W = Wk; C = g_K; }
    else                      { A = v; W = Wv; C = g_V; }
    gemm_body(A, W, C);
}

__global__ void __launch_bounds__(128) out_gemm_kernel(
    const float* __restrict__ Wo, float* __restrict__ out)
{
    gemm_body(g_O, Wo, out);
}

// ---------------------------------------------------------------------------
// Flash attention: CTA = (b, h, 128-query tile), 4 warps.
// Warp w owns rows w*32..w*32+31 (2 row-frags), all 64 keys -> warp-local
// softmax. Q a-frags hoisted to registers for the whole kernel (staged once
// through the K buffer); K/V frags loaded once per (k,n) and reused for both
// row-frags. KSTR=68 / VSTR=72 keep all frag loads conflict-free.
// ---------------------------------------------------------------------------
#define FKV  64
#define KSTR 68
#define VSTR 72

__global__ void __launch_bounds__(128) flash_kernel()
{
    __shared__ float Ks[FKV * KSTR];   // also used to stage Q at start
    __shared__ float Vs[FKV * VSTR];

    const int tid  = threadIdx.x;
    const int w    = tid >> 5;
    const int lane = tid & 31;
    const int g    = lane >> 2;
    const int tg   = lane & 3;
    const int b    = blockIdx.z;
    const int h    = blockIdx.y;
    const int q0   = blockIdx.x * 128;
    const size_t base = ((size_t)b * SEQ) * HIDD + (size_t)h * HD;

    // ---- hoist Q fragments into registers (two 64-row staging passes) ----
    uint32_t qf[8][2][4];
#pragma unroll
    for (int ch = 0; ch < 2; ch++) {
#pragma unroll
        for (int t = 0; t < 8; t++) {
            int idx = t * 128 + tid;
            int r = idx >> 4, c = (idx & 15) << 2;
            float4 q4 = *(const float4*)(&g_Q[base + (size_t)(q0 + ch * 64 + r) * HIDD + c]);
            *(float4*)(&Ks[r * KSTR + c]) = make_float4(
                f2tff(q4.x * 0.125f), f2tff(q4.y * 0.125f),
                f2tff(q4.z * 0.125f), f2tff(q4.w * 0.125f));
        }
        __syncthreads();
        if ((w >> 1) == ch) {
            int lr = (w & 1) * 32;
#pragma unroll
            for (int kk = 0; kk < 8; kk++) {
                int kb = kk * 8;
#pragma unroll
                for (int mf = 0; mf < 2; mf++) {
                    int r0 = lr + mf * 16 + g;
                    qf[kk][mf][0] = __float_as_uint(Ks[(r0)     * KSTR + kb + tg]);
                    qf[kk][mf][1] = __float_as_uint(Ks[(r0 + 8) * KSTR + kb + tg]);
                    qf[kk][mf][2] = __float_as_uint(Ks[(r0)     * KSTR + kb + tg + 4]);
                    qf[kk][mf][3] = __float_as_uint(Ks[(r0 + 8) * KSTR + kb + tg + 4]);
                }
            }
        }
        __syncthreads();
    }

    float o[2][8][4] = {};
    float m[2][2] = {{-1e30f, -1e30f}, {-1e30f, -1e30f}};
    float l[2][2] = {{0.0f, 0.0f}, {0.0f, 0.0f}};

    for (int k0 = 0; k0 < SEQ; k0 += FKV) {
        __syncthreads();   // previous iter's reads of Ks/Vs complete
        // stage K, V (64x64 each)
#pragma unroll
        for (int t = 0; t < 8; t++) {
            int idx = t * 128 + tid;
            int r = idx >> 4, c = (idx & 15) << 2;
            size_t gp = base + (size_t)(k0 + r) * HIDD + c;
            float4 k4 = *(const float4*)(&g_K[gp]);
            *(float4*)(&Ks[r * KSTR + c]) = cvt4(k4);
            float4 v4 = *(const float4*)(&g_V[gp]);
            *(float4*)(&Vs[r * VSTR + c]) = cvt4(v4);
        }
        __syncthreads();

        // ---- S = Q @ K^T : 32 rows x 64 keys per warp ----
        float s[2][8][4] = {};
#pragma unroll
        for (int kk = 0; kk < 8; kk++) {
            int kb = kk * 8;
#pragma unroll
            for (int nf = 0; nf < 8; nf++) {
                int n = nf * 8 + g;
                uint32_t bf[2];
                bf[0] = __float_as_uint(Ks[n * KSTR + kb + tg]);
                bf[1] = __float_as_uint(Ks[n * KSTR + kb + tg + 4]);
                mma_tf32(s[0][nf], qf[kk][0], bf);
                mma_tf32(s[1][nf], qf[kk][1], bf);
            }
        }

        // ---- online softmax per row-frag (warp-local quad shuffles) ----
#pragma unroll
        for (int mf = 0; mf < 2; mf++) {
            float tlo = -1e30f, thi = -1e30f;
#pragma unroll
            for (int nf = 0; nf < 8; nf++) {
                tlo = fmaxf(tlo, fmaxf(s[mf][nf][0], s[mf][nf][1]));
                thi = fmaxf(thi, fmaxf(s[mf][nf][2], s[mf][nf][3]));
            }
            tlo = fmaxf(tlo, __shfl_xor_sync(0xffffffffu, tlo, 1));
            tlo = fmaxf(tlo, __shfl_xor_sync(0xffffffffu, tlo, 2));
            thi = fmaxf(thi, __shfl_xor_sync(0xffffffffu, thi, 1));
            thi = fmaxf(thi, __shfl_xor_sync(0xffffffffu, thi, 2));

            float mn_lo = fmaxf(m[mf][0], tlo);
            float mn_hi = fmaxf(m[mf][1], thi);
            float corr_lo = __expf(m[mf][0] - mn_lo);
            float corr_hi = __expf(m[mf][1] - mn_hi);
            m[mf][0] = mn_lo; m[mf][1] = mn_hi;

            float sum_lo = 0.0f, sum_hi = 0.0f;
#pragma unroll
            for (int nf = 0; nf < 8; nf++) {
                s[mf][nf][0] = __expf(s[mf][nf][0] - mn_lo);
                s[mf][nf][1] = __expf(s[mf][nf][1] - mn_lo);
                s[mf][nf][2] = __expf(s[mf][nf][2] - mn_hi);
                s[mf][nf][3] = __expf(s[mf][nf][3] - mn_hi);
                sum_lo += s[mf][nf][0] + s[mf][nf][1];
                sum_hi += s[mf][nf][2] + s[mf][nf][3];
            }
            sum_lo += __shfl_xor_sync(0xffffffffu, sum_lo, 1);
            sum_lo += __shfl_xor_sync(0xffffffffu, sum_lo, 2);
            sum_hi += __shfl_xor_sync(0xffffffffu, sum_hi, 1);
            sum_hi += __shfl_xor_sync(0xffffffffu, sum_hi, 2);
            l[mf][0] = l[mf][0] * corr_lo + sum_lo;
            l[mf][1] = l[mf][1] * corr_hi + sum_hi;

#pragma unroll
            for (int nf = 0; nf < 8; nf++) {
                o[mf][nf][0] *= corr_lo;  o[mf][nf][1] *= corr_lo;
                o[mf][nf][2] *= corr_hi;  o[mf][nf][3] *= corr_hi;
                s[mf][nf][0] = f2tff(s[mf][nf][0]);
                s[mf][nf][1] = f2tff(s[mf][nf][1]);
                s[mf][nf][2] = f2tff(s[mf][nf][2]);
                s[mf][nf][3] = f2tff(s[mf][nf][3]);
            }
        }

        // ---- O += P @ V : C-layout -> A-layout via width-4 shuffles ----
#pragma unroll
        for (int kc = 0; kc < 8; kc++) {
            int kb = kc * 8;
            int src1 = tg >> 1, src2 = src1 + 2;
            bool odd = (tg & 1);
            uint32_t af[2][4];
#pragma unroll
            for (int mf = 0; mf < 2; mf++) {
                float e, d2;
                e  = __shfl_sync(0xffffffffu, s[mf][kc][0], src1, 4);
                d2 = __shfl_sync(0xffffffffu, s[mf][kc][1], src1, 4);
                af[mf][0] = __float_as_uint(odd ? d2 : e);
                e  = __shfl_sync(0xffffffffu, s[mf][kc][2], src1, 4);
                d2 = __shfl_sync(0xffffffffu, s[mf][kc][3], src1, 4);
                af[mf][1] = __float_as_uint(odd ? d2 : e);
                e  = __shfl_sync(0xffffffffu, s[mf][kc][0], src2, 4);
                d2 = __shfl_sync(0xffffffffu, s[mf][kc][1], src2, 4);
                af[mf][2] = __float_as_uint(odd ? d2 : e);
                e  = __shfl_sync(0xffffffffu, s[mf][kc][2], src2, 4);
                d2 = __shfl_sync(0xffffffffu, s[mf][kc][3], src2, 4);
                af[mf][3] = __float_as_uint(odd ? d2 : e);
            }
#pragma unroll
            for (int nf = 0; nf < 8; nf++) {
                int c0 = nf * 8 + g;
                uint32_t bf[2];
                bf[0] = __float_as_uint(Vs[(kb + tg)     * VSTR + c0]);
                bf[1] = __float_as_uint(Vs[(kb + tg + 4) * VSTR + c0]);
                mma_tf32(o[0][nf], af[0], bf);
                mma_tf32(o[1][nf], af[1], bf);
            }
        }
    }

    // ---- epilogue: normalize + write O ----
#pragma unroll
    for (int mf = 0; mf < 2; mf++) {
        float inv0 = 1.0f / l[mf][0];
        float inv1 = 1.0f / l[mf][1];
        size_t row = (size_t)(q0 + w * 32 + mf * 16 + g);
#pragma unroll
        for (int nf = 0; nf < 8; nf++) {
            int col = nf * 8 + 2 * tg;
            *(float2*)(&g_O[base + row * HIDD + col]) =
                make_float2(o[mf][nf][0] * inv0, o[mf][nf][1] * inv0);
            *(float2*)(&g_O[base + (row + 8) * HIDD + col]) =
                make_float2(o[mf][nf][2] * inv1, o[mf][nf][3] * inv1);
        }
    }
}

// ---------------------------------------------------------------------------
// Launch: 3 dependent kernels, graph-capturable, allocation-free.
// ---------------------------------------------------------------------------
extern "C" void kernel_launch(void* const* d_in, const int* in_sizes, int n_in,
                              void* d_out, int out_size)
{
    const float* q  = (const float*)d_in[0];
    const float* k  = (const float*)d_in[1];
    const float* v  = (const float*)d_in[2];
    const float* Wq = (const float*)d_in[3];
    const float* Wk = (const float*)d_in[4];
    const float* Wv = (const float*)d_in[5];
    const float* Wo = (const float*)d_in[6];
    float* out = (float*)d_out;
    (void)in_sizes; (void)n_in; (void)out_size;

    dim3 gproj(GN / 128, GM / 128, 3);          // 8 x 64 x 3
    qkv_gemm_kernel<<<gproj, 128>>>(q, k, v, Wq, Wk, Wv);

    dim3 gattn(SEQ / 128, NH, BATCH);           // 16 x 16 x 4
    flash_kernel<<<gattn, 128>>>();

    dim3 gout(GN / 128, GM / 128);              // 8 x 64
    out_gemm_kernel<<<gout, 128>>>(Wo, out);
}

// round 12
// speedup vs baseline: 4.1272x; 1.2296x over previous
#include <cuda_runtime.h>
#include <cuda_fp16.h>
#include <stdint.h>

// Problem constants
#define BATCH 4
#define SEQ   2048
#define HIDD  1024
#define NH    16
#define HD    64

#define GM (BATCH*SEQ)
#define GK HIDD
#define GN HIDD

// Scratch (__device__ globals; allocations forbidden). All fp16.
__device__ __half g_Q[BATCH*SEQ*HIDD];   // pre-scaled by 1/8 at projection
__device__ __half g_K[BATCH*SEQ*HIDD];
__device__ __half g_V[BATCH*SEQ*HIDD];
__device__ __half g_O[BATCH*SEQ*HIDD];

// ---------------------------------------------------------------------------
// Helpers
// ---------------------------------------------------------------------------
// D += A(m16k16,row) * B(k16n8,col), fp16 in, fp32 accum
__device__ __forceinline__ void mma_f16(float* d, const uint32_t* a, const uint32_t* b) {
    asm volatile(
        "mma.sync.aligned.m16n8k16.row.col.f32.f16.f16.f32 "
        "{%0,%1,%2,%3}, {%4,%5,%6,%7}, {%8,%9}, {%0,%1,%2,%3};"
        : "+f"(d[0]), "+f"(d[1]), "+f"(d[2]), "+f"(d[3])
        : "r"(a[0]), "r"(a[1]), "r"(a[2]), "r"(a[3]), "r"(b[0]), "r"(b[1]));
}
__device__ __forceinline__ uint32_t h2pack(float lo, float hi) {
    __half2 h = __floats2half2_rn(lo, hi);
    return *reinterpret_cast<uint32_t*>(&h);
}
__device__ __forceinline__ uint32_t prmt(uint32_t a, uint32_t b, uint32_t sel) {
    uint32_t d;
    asm("prmt.b32 %0, %1, %2, %3;" : "=r"(d) : "r"(a), "r"(b), "r"(sel));
    return d;
}

// ---------------------------------------------------------------------------
// FP16 GEMM: C[M,N] = A[M,K] @ W[K,N]. CTA 128x128, 4 warps (2x2),
// warp tile 64x64 (4mf x 8nf), TK=16 (one k16 mma step/iter), double-buffered.
// Smem: k-pair-major half2 arrays, stride 136 words (136%32==8):
//   As2[k2][r] -> a-frag bank (8*k2 + r)%32 distinct per warp
//   Bs2[k2][n] -> b-frag bank (8*k2 + n)%32 distinct per warp
// Staging STS verified conflict-free per-instruction.
// ---------------------------------------------------------------------------
#define GSTR 136

template<bool AHALF, bool OHALF>
__device__ __forceinline__ void gemm_core(const void* __restrict__ Ain,
                                          const float* __restrict__ W,
                                          void* __restrict__ Cout,
                                          float cscale)
{
    __shared__ uint32_t As[2][8 * GSTR];
    __shared__ uint32_t Bs[2][8 * GSTR];

    const int tid  = threadIdx.x;
    const int w    = tid >> 5;
    const int lane = tid & 31;
    const int g    = lane >> 2;
    const int tg   = lane & 3;
    const int wm   = w >> 1;
    const int wn   = w & 1;
    const int bm   = blockIdx.y * 128;
    const int bn   = blockIdx.x * 128;

    float acc[4][8][4] = {};
    float4 paf[4];
    uint4  pah[2];
    float4 pb[4];

    // prefetch-load tile k0 into registers
    auto LD = [&](int k0) {
        if (AHALF) {
            const __half* A = (const __half*)Ain;
            const uint4* ap = (const uint4*)(A + (size_t)(bm + tid) * GK + k0);
            pah[0] = ap[0]; pah[1] = ap[1];
        } else {
            const float* A = (const float*)Ain;
            const float4* ap = (const float4*)(A + (size_t)(bm + tid) * GK + k0);
            paf[0] = ap[0]; paf[1] = ap[1]; paf[2] = ap[2]; paf[3] = ap[3];
        }
#pragma unroll
        for (int p = 0; p < 2; p++) {
            int qi = p * 128 + tid;
            int nq = qi & 31, kq = qi >> 5;
            const float* w0 = W + (size_t)(k0 + 2 * kq) * GN + bn + 4 * nq;
            pb[2 * p]     = *(const float4*)w0;
            pb[2 * p + 1] = *(const float4*)(w0 + GN);
        }
    };
    // store prefetched registers into smem buffer
    auto ST = [&](int buf) {
        if (AHALF) {
            const uint32_t* u = (const uint32_t*)pah;
#pragma unroll
            for (int j = 0; j < 8; j++) As[buf][j * GSTR + tid] = u[j];
        } else {
            const float* f = (const float*)paf;
#pragma unroll
            for (int j = 0; j < 8; j++)
                As[buf][j * GSTR + tid] = h2pack(f[2 * j], f[2 * j + 1]);
        }
#pragma unroll
        for (int p = 0; p < 2; p++) {
            int qi = p * 128 + tid;
            int nq = qi & 31, kq = qi >> 5;
            uint4 v;
            v.x = h2pack(pb[2 * p].x, pb[2 * p + 1].x);
            v.y = h2pack(pb[2 * p].y, pb[2 * p + 1].y);
            v.z = h2pack(pb[2 * p].z, pb[2 * p + 1].z);
            v.w = h2pack(pb[2 * p].w, pb[2 * p + 1].w);
            *(uint4*)&Bs[buf][kq * GSTR + 4 * nq] = v;
        }
    };

    LD(0); ST(0);
    __syncthreads();

    for (int it = 0; it < 64; it++) {
        const int cur = it & 1;
        if (it < 63) LD((it + 1) * 16);

        uint32_t af[4][4], bf[8][2];
#pragma unroll
        for (int mf = 0; mf < 4; mf++) {
            int r0 = wm * 64 + mf * 16 + g;
            af[mf][0] = As[cur][(tg)     * GSTR + r0];
            af[mf][1] = As[cur][(tg)     * GSTR + r0 + 8];
            af[mf][2] = As[cur][(tg + 4) * GSTR + r0];
            af[mf][3] = As[cur][(tg + 4) * GSTR + r0 + 8];
        }
#pragma unroll
        for (int nf = 0; nf < 8; nf++) {
            int c0 = wn * 64 + nf * 8 + g;
            bf[nf][0] = Bs[cur][(tg)     * GSTR + c0];
            bf[nf][1] = Bs[cur][(tg + 4) * GSTR + c0];
        }
#pragma unroll
        for (int mf = 0; mf < 4; mf++)
#pragma unroll
            for (int nf = 0; nf < 8; nf++)
                mma_f16(acc[mf][nf], af[mf], bf[nf]);

        if (it < 63) ST(cur ^ 1);
        __syncthreads();
    }

    // Epilogue (C-layout: rows g/g+8, cols 2tg,2tg+1)
#pragma unroll
    for (int mf = 0; mf < 4; mf++) {
        int r0 = bm + wm * 64 + mf * 16 + g;
#pragma unroll
        for (int nf = 0; nf < 8; nf++) {
            int c0 = bn + wn * 64 + nf * 8 + 2 * tg;
            if (OHALF) {
                __half* Ch = (__half*)Cout;
                *(uint32_t*)(Ch + (size_t)r0 * GN + c0) =
                    h2pack(acc[mf][nf][0] * cscale, acc[mf][nf][1] * cscale);
                *(uint32_t*)(Ch + (size_t)(r0 + 8) * GN + c0) =
                    h2pack(acc[mf][nf][2] * cscale, acc[mf][nf][3] * cscale);
            } else {
                float* Cf = (float*)Cout;
                *(float2*)(Cf + (size_t)r0 * GN + c0) =
                    make_float2(acc[mf][nf][0], acc[mf][nf][1]);
                *(float2*)(Cf + (size_t)(r0 + 8) * GN + c0) =
                    make_float2(acc[mf][nf][2], acc[mf][nf][3]);
            }
        }
    }
}

__global__ void __launch_bounds__(128) qkv_gemm_kernel(
    const float* __restrict__ q, const float* __restrict__ k, const float* __restrict__ v,
    const float* __restrict__ Wq, const float* __restrict__ Wk, const float* __restrict__ Wv)
{
    if (blockIdx.z == 0)      gemm_core<false, true>(q, Wq, g_Q, 0.125f); // fold 1/sqrt(D)
    else if (blockIdx.z == 1) gemm_core<false, true>(k, Wk, g_K, 1.0f);
    else                      gemm_core<false, true>(v, Wv, g_V, 1.0f);
}

__global__ void __launch_bounds__(128) out_gemm_kernel(
    const float* __restrict__ Wo, float* __restrict__ out)
{
    gemm_core<true, false>(g_O, Wo, out, 1.0f);
}

// ---------------------------------------------------------------------------
// Flash attention, fp16 m16n8k16. CTA = (b,h,128-q-tile), 4 warps; warp owns
// 32 rows x all 64 keys -> warp-local softmax (quad shuffles). Q a-frags
// hoisted to registers (staged once via Ks buffer). P stays in registers:
// S C-layout pairs ARE the PV A-fragment half2 pairs (FA2 identity).
// Smem stride 72 words (72%32==8): all frag LDS conflict-free.
// ---------------------------------------------------------------------------
#define FSTR 72

__global__ void __launch_bounds__(128) flash_kernel()
{
    __shared__ uint32_t Ks[32 * FSTR];   // [k2][key] half2; also stages Q
    __shared__ uint32_t Vs[32 * FSTR];   // [kv-pair][d] half2

    const int tid  = threadIdx.x;
    const int w    = tid >> 5;
    const int lane = tid & 31;
    const int g    = lane >> 2;
    const int tg   = lane & 3;
    const int b    = blockIdx.z;
    const int h    = blockIdx.y;
    const int q0   = blockIdx.x * 128;
    const size_t base = ((size_t)b * SEQ) * HIDD + (size_t)h * HD;

    // ---- hoist Q fragments (Q already scaled by 1/8): two 64-row passes ----
    uint32_t qf[4][2][4];
#pragma unroll
    for (int ch = 0; ch < 2; ch++) {
#pragma unroll
        for (int p = 0; p < 4; p++) {
            int idx = p * 128 + tid;
            int n = idx & 63, cq = idx >> 6;          // cq 0..7
            uint4 u = *(const uint4*)(&g_Q[base + (size_t)(q0 + ch * 64 + n) * HIDD + cq * 8]);
            Ks[(4 * cq + 0) * FSTR + n] = u.x;
            Ks[(4 * cq + 1) * FSTR + n] = u.y;
            Ks[(4 * cq + 2) * FSTR + n] = u.z;
            Ks[(4 * cq + 3) * FSTR + n] = u.w;
        }
        __syncthreads();
        if ((w >> 1) == ch) {
            int lr = (w & 1) * 32;
#pragma unroll
            for (int kk = 0; kk < 4; kk++)
#pragma unroll
                for (int mf = 0; mf < 2; mf++) {
                    int r0 = lr + mf * 16 + g;
                    qf[kk][mf][0] = Ks[(8 * kk + tg)     * FSTR + r0];
                    qf[kk][mf][1] = Ks[(8 * kk + tg)     * FSTR + r0 + 8];
                    qf[kk][mf][2] = Ks[(8 * kk + tg + 4) * FSTR + r0];
                    qf[kk][mf][3] = Ks[(8 * kk + tg + 4) * FSTR + r0 + 8];
                }
        }
        __syncthreads();
    }

    float o[2][8][4] = {};
    float m[2][2] = {{-1e30f, -1e30f}, {-1e30f, -1e30f}};
    float l[2][2] = {{0.0f, 0.0f}, {0.0f, 0.0f}};

    for (int k0 = 0; k0 < SEQ; k0 += 64) {
        __syncthreads();
        // ---- stage K [k2][key] ----
#pragma unroll
        for (int p = 0; p < 4; p++) {
            int idx = p * 128 + tid;
            int n = idx & 63, cq = idx >> 6;
            uint4 u = *(const uint4*)(&g_K[base + (size_t)(k0 + n) * HIDD + cq * 8]);
            Ks[(4 * cq + 0) * FSTR + n] = u.x;
            Ks[(4 * cq + 1) * FSTR + n] = u.y;
            Ks[(4 * cq + 2) * FSTR + n] = u.z;
            Ks[(4 * cq + 3) * FSTR + n] = u.w;
        }
        // ---- stage V [key-pair][d] (prmt interleave of adjacent key rows) ----
#pragma unroll
        for (int p = 0; p < 2; p++) {
            int idx = p * 128 + tid;
            int k2 = idx >> 3, dq = idx & 7;
            const uint4 ua = *(const uint4*)(&g_V[base + (size_t)(k0 + 2 * k2)     * HIDD + dq * 8]);
            const uint4 ub = *(const uint4*)(&g_V[base + (size_t)(k0 + 2 * k2 + 1) * HIDD + dq * 8]);
            uint4 v0, v1;
            v0.x = prmt(ua.x, ub.x, 0x5410); v0.y = prmt(ua.x, ub.x, 0x7632);
            v0.z = prmt(ua.y, ub.y, 0x5410); v0.w = prmt(ua.y, ub.y, 0x7632);
            v1.x = prmt(ua.z, ub.z, 0x5410); v1.y = prmt(ua.z, ub.z, 0x7632);
            v1.z = prmt(ua.w, ub.w, 0x5410); v1.w = prmt(ua.w, ub.w, 0x7632);
            *(uint4*)&Vs[k2 * FSTR + 8 * dq]     = v0;
            *(uint4*)&Vs[k2 * FSTR + 8 * dq + 4] = v1;
        }
        __syncthreads();

        // ---- S = Q @ K^T : 32 rows x 64 keys per warp ----
        float s[2][8][4] = {};
#pragma unroll
        for (int kk = 0; kk < 4; kk++) {
#pragma unroll
            for (int nf = 0; nf < 8; nf++) {
                int n = nf * 8 + g;
                uint32_t bf[2];
                bf[0] = Ks[(8 * kk + tg)     * FSTR + n];
                bf[1] = Ks[(8 * kk + tg + 4) * FSTR + n];
                mma_f16(s[0][nf], qf[kk][0], bf);
                mma_f16(s[1][nf], qf[kk][1], bf);
            }
        }

        // ---- online softmax per row-frag (quad shuffles) ----
#pragma unroll
        for (int mf = 0; mf < 2; mf++) {
            float tlo = -1e30f, thi = -1e30f;
#pragma unroll
            for (int nf = 0; nf < 8; nf++) {
                tlo = fmaxf(tlo, fmaxf(s[mf][nf][0], s[mf][nf][1]));
                thi = fmaxf(thi, fmaxf(s[mf][nf][2], s[mf][nf][3]));
            }
            tlo = fmaxf(tlo, __shfl_xor_sync(0xffffffffu, tlo, 1));
            tlo = fmaxf(tlo, __shfl_xor_sync(0xffffffffu, tlo, 2));
            thi = fmaxf(thi, __shfl_xor_sync(0xffffffffu, thi, 1));
            thi = fmaxf(thi, __shfl_xor_sync(0xffffffffu, thi, 2));

            float mn_lo = fmaxf(m[mf][0], tlo);
            float mn_hi = fmaxf(m[mf][1], thi);
            float corr_lo = __expf(m[mf][0] - mn_lo);
            float corr_hi = __expf(m[mf][1] - mn_hi);
            m[mf][0] = mn_lo; m[mf][1] = mn_hi;

            float sum_lo = 0.0f, sum_hi = 0.0f;
#pragma unroll
            for (int nf = 0; nf < 8; nf++) {
                s[mf][nf][0] = __expf(s[mf][nf][0] - mn_lo);
                s[mf][nf][1] = __expf(s[mf][nf][1] - mn_lo);
                s[mf][nf][2] = __expf(s[mf][nf][2] - mn_hi);
                s[mf][nf][3] = __expf(s[mf][nf][3] - mn_hi);
                sum_lo += s[mf][nf][0] + s[mf][nf][1];
                sum_hi += s[mf][nf][2] + s[mf][nf][3];
            }
            sum_lo += __shfl_xor_sync(0xffffffffu, sum_lo, 1);
            sum_lo += __shfl_xor_sync(0xffffffffu, sum_lo, 2);
            sum_hi += __shfl_xor_sync(0xffffffffu, sum_hi, 1);
            sum_hi += __shfl_xor_sync(0xffffffffu, sum_hi, 2);
            l[mf][0] = l[mf][0] * corr_lo + sum_lo;
            l[mf][1] = l[mf][1] * corr_hi + sum_hi;

#pragma unroll
            for (int nf = 0; nf < 8; nf++) {
                o[mf][nf][0] *= corr_lo;  o[mf][nf][1] *= corr_lo;
                o[mf][nf][2] *= corr_hi;  o[mf][nf][3] *= corr_hi;
            }
        }

        // ---- O += P @ V : S C-layout pairs == PV A-frag half2 (no shuffles) ----
#pragma unroll
        for (int kc = 0; kc < 4; kc++) {
            uint32_t af[2][4];
#pragma unroll
            for (int mf = 0; mf < 2; mf++) {
                af[mf][0] = h2pack(s[mf][2 * kc][0],     s[mf][2 * kc][1]);
                af[mf][1] = h2pack(s[mf][2 * kc][2],     s[mf][2 * kc][3]);
                af[mf][2] = h2pack(s[mf][2 * kc + 1][0], s[mf][2 * kc + 1][1]);
                af[mf][3] = h2pack(s[mf][2 * kc + 1][2], s[mf][2 * kc + 1][3]);
            }
#pragma unroll
            for (int nf = 0; nf < 8; nf++) {
                int d = nf * 8 + g;
                uint32_t bf[2];
                bf[0] = Vs[(8 * kc + tg)     * FSTR + d];
                bf[1] = Vs[(8 * kc + tg + 4) * FSTR + d];
                mma_f16(o[0][nf], af[0], bf);
                mma_f16(o[1][nf], af[1], bf);
            }
        }
    }

    // ---- epilogue: normalize, write half O ----
#pragma unroll
    for (int mf = 0; mf < 2; mf++) {
        float inv0 = 1.0f / l[mf][0];
        float inv1 = 1.0f / l[mf][1];
        size_t row = (size_t)(q0 + w * 32 + mf * 16 + g);
#pragma unroll
        for (int nf = 0; nf < 8; nf++) {
            int col = nf * 8 + 2 * tg;
            *(uint32_t*)(&g_O[base + row * HIDD + col]) =
                h2pack(o[mf][nf][0] * inv0, o[mf][nf][1] * inv0);
            *(uint32_t*)(&g_O[base + (row + 8) * HIDD + col]) =
                h2pack(o[mf][nf][2] * inv1, o[mf][nf][3] * inv1);
        }
    }
}

// ---------------------------------------------------------------------------
// Launch: 3 dependent kernels, graph-capturable, allocation-free.
// ---------------------------------------------------------------------------
extern "C" void kernel_launch(void* const* d_in, const int* in_sizes, int n_in,
                              void* d_out, int out_size)
{
    const float* q  = (const float*)d_in[0];
    const float* k  = (const float*)d_in[1];
    const float* v  = (const float*)d_in[2];
    const float* Wq = (const float*)d_in[3];
    const float* Wk = (const float*)d_in[4];
    const float* Wv = (const float*)d_in[5];
    const float* Wo = (const float*)d_in[6];
    float* out = (float*)d_out;
    (void)in_sizes; (void)n_in; (void)out_size;

    dim3 gproj(GN / 128, GM / 128, 3);          // 8 x 64 x 3
    qkv_gemm_kernel<<<gproj, 128>>>(q, k, v, Wq, Wk, Wv);

    dim3 gattn(SEQ / 128, NH, BATCH);           // 16 x 16 x 4
    flash_kernel<<<gattn, 128>>>();

    dim3 gout(GN / 128, GM / 128);              // 8 x 64
    out_gemm_kernel<<<gout, 128>>>(Wo, out);
}

// round 15
// speedup vs baseline: 7.5598x; 1.8317x over previous
#include <cuda_runtime.h>
#include <cuda_fp16.h>
#include <stdint.h>

// Problem constants
#define BATCH 4
#define SEQ   2048
#define HIDD  1024
#define NH    16
#define HD    64

#define GM (BATCH*SEQ)
#define GK HIDD
#define GN HIDD

// ---------------------------------------------------------------------------
// Scratch (__device__ globals; allocations forbidden). All fp16.
// ---------------------------------------------------------------------------
__device__ __half g_Q[BATCH*SEQ*HIDD];   // pre-scaled by 1/8 at projection
__device__ __half g_K[BATCH*SEQ*HIDD];
__device__ __half g_V[BATCH*SEQ*HIDD];
__device__ __half g_O[BATCH*SEQ*HIDD];
// fp16 copies of the fp32 harness inputs (made by convert_kernel)
__device__ __half g_qh[GM*GK];
__device__ __half g_kh[GM*GK];
__device__ __half g_vh[GM*GK];
__device__ __half g_Wqh[GK*GN];
__device__ __half g_Wkh[GK*GN];
__device__ __half g_Wvh[GK*GN];
__device__ __half g_Woh[GK*GN];

// ---------------------------------------------------------------------------
// Helpers
// ---------------------------------------------------------------------------
__device__ __forceinline__ void mma_f16(float* d, const uint32_t* a, const uint32_t* b) {
    asm volatile(
        "mma.sync.aligned.m16n8k16.row.col.f32.f16.f16.f32 "
        "{%0,%1,%2,%3}, {%4,%5,%6,%7}, {%8,%9}, {%0,%1,%2,%3};"
        : "+f"(d[0]), "+f"(d[1]), "+f"(d[2]), "+f"(d[3])
        : "r"(a[0]), "r"(a[1]), "r"(a[2]), "r"(a[3]), "r"(b[0]), "r"(b[1]));
}
__device__ __forceinline__ uint32_t h2pack(float lo, float hi) {
    __half2 h = __floats2half2_rn(lo, hi);
    return *reinterpret_cast<uint32_t*>(&h);
}
#define LDSM4(R, addr) \
    asm volatile("ldmatrix.sync.aligned.m8n8.x4.shared.b16 {%0,%1,%2,%3}, [%4];" \
                 : "=r"((R)[0]), "=r"((R)[1]), "=r"((R)[2]), "=r"((R)[3]) : "r"(addr))
#define LDSM4T(R, addr) \
    asm volatile("ldmatrix.sync.aligned.m8n8.x4.trans.shared.b16 {%0,%1,%2,%3}, [%4];" \
                 : "=r"((R)[0]), "=r"((R)[1]), "=r"((R)[2]), "=r"((R)[3]) : "r"(addr))
#define CPASYNC16(s, g) \
    asm volatile("cp.async.ca.shared.global [%0], [%1], 16;" :: "r"(s), "l"(g))
#define CPCOMMIT() asm volatile("cp.async.commit_group;" ::: "memory")
#define CPWAIT0()  asm volatile("cp.async.wait_group 0;" ::: "memory")
#define CPWAIT1()  asm volatile("cp.async.wait_group 1;" ::: "memory")
#define CPWAIT2()  asm volatile("cp.async.wait_group 2;" ::: "memory")

// ---------------------------------------------------------------------------
// Convert kernel: fp32 inputs/weights -> fp16 device copies (one pass).
// ---------------------------------------------------------------------------
__global__ void __launch_bounds__(256) convert_kernel(
    const float4* q, const float4* k, const float4* v,
    const float4* wq, const float4* wk, const float4* wv, const float4* wo)
{
    const float4* src; uint2* dst; int n4;
    switch (blockIdx.z) {
        case 0: src = q;  dst = (uint2*)g_qh;  n4 = GM*GK/4; break;
        case 1: src = k;  dst = (uint2*)g_kh;  n4 = GM*GK/4; break;
        case 2: src = v;  dst = (uint2*)g_vh;  n4 = GM*GK/4; break;
        case 3: src = wq; dst = (uint2*)g_Wqh; n4 = GK*GN/4; break;
        case 4: src = wk; dst = (uint2*)g_Wkh; n4 = GK*GN/4; break;
        case 5: src = wv; dst = (uint2*)g_Wvh; n4 = GK*GN/4; break;
        default: src = wo; dst = (uint2*)g_Woh; n4 = GK*GN/4; break;
    }
    for (int i = blockIdx.x * blockDim.x + threadIdx.x; i < n4;
         i += gridDim.x * blockDim.x) {
        float4 f = src[i];
        uint2 u;
        u.x = h2pack(f.x, f.y);
        u.y = h2pack(f.z, f.w);
        dst[i] = u;
    }
}

// ---------------------------------------------------------------------------
// FP16 GEMM, cp.async 3-stage + ldmatrix. C[M,N] = A[M,K] @ W[K,N], all half.
// CTA 128x128, 256 threads (8 warps 2x4), warp tile 64x32, TK=32.
// Smem/stage: A [128 rows x 64B +16 pad = 80B], B [32 k-rows x 256B +16 = 272B].
// ---------------------------------------------------------------------------
#define STG_BYTES 18944               // 128*80 + 32*272
#define GEMM_SMEM (3 * STG_BYTES)     // 56832

template<bool OHALF>
__device__ __forceinline__ void gemm_core(const __half* __restrict__ Ah,
                                          const __half* __restrict__ Wh,
                                          void* __restrict__ Cout,
                                          float cscale)
{
    extern __shared__ __align__(16) char smem[];
    const uint32_t sb = (uint32_t)__cvta_generic_to_shared(smem);

    const int tid  = threadIdx.x;
    const int w    = tid >> 5;
    const int lane = tid & 31;
    const int g    = lane >> 2;
    const int tg   = lane & 3;
    const int wm   = w >> 2;          // 0..1 -> 64 rows
    const int wn   = w & 3;           // 0..3 -> 32 cols
    const int bm   = blockIdx.y * 128;
    const int bn   = blockIdx.x * 128;
    // ldmatrix lane mapping (A non-trans and B trans share it)
    const int arow = (lane & 7) + ((lane >> 3) & 1) * 8;
    const int achk = (lane >> 4) & 1;

    float acc[4][4][4] = {};

#define G_ISSUE(s, k0) do {                                                     \
        uint32_t sA = sb + (s) * STG_BYTES;                                     \
        uint32_t sB = sA + 10240;                                               \
        _Pragma("unroll")                                                       \
        for (int t = 0; t < 2; t++) {                                           \
            int c = t * 256 + tid; int r = c >> 2, col = c & 3;                 \
            CPASYNC16(sA + r * 80 + col * 16,                                   \
                      Ah + (size_t)(bm + r) * GK + (k0) + col * 8);             \
        }                                                                       \
        _Pragma("unroll")                                                       \
        for (int t = 0; t < 2; t++) {                                           \
            int c = t * 256 + tid; int r = c >> 4, cn = c & 15;                 \
            CPASYNC16(sB + r * 272 + cn * 16,                                   \
                      Wh + (size_t)((k0) + r) * GN + bn + cn * 8);              \
        }                                                                       \
        CPCOMMIT();                                                             \
    } while (0)

    G_ISSUE(0, 0);
    G_ISSUE(1, 32);

    for (int it = 0; it < 32; it++) {
        const int cur = it - (it / 3) * 3;          // it % 3
        if (it + 2 < 32) {
            int nxt = (it + 2) - ((it + 2) / 3) * 3;
            G_ISSUE(nxt, (it + 2) * 32);
            CPWAIT2();
        } else if (it + 1 < 32) {
            CPWAIT1();
        } else {
            CPWAIT0();
        }
        __syncthreads();

        uint32_t sA = sb + cur * STG_BYTES;
        uint32_t sB = sA + 10240;
#pragma unroll
        for (int kk = 0; kk < 2; kk++) {
            uint32_t a[4][4], bq[2][4];
#pragma unroll
            for (int mf = 0; mf < 4; mf++)
                LDSM4(a[mf], sA + (wm * 64 + mf * 16 + arow) * 80 + kk * 32 + achk * 16);
#pragma unroll
            for (int nf2 = 0; nf2 < 2; nf2++)
                LDSM4T(bq[nf2], sB + (kk * 16 + arow) * 272 + wn * 64 + nf2 * 32 + achk * 16);
#pragma unroll
            for (int mf = 0; mf < 4; mf++)
#pragma unroll
                for (int n8 = 0; n8 < 4; n8++)
                    mma_f16(acc[mf][n8], a[mf], &bq[n8 >> 1][(n8 & 1) * 2]);
        }
        __syncthreads();
    }
#undef G_ISSUE

    // Epilogue: C-layout (rows g/g+8, cols 2tg,2tg+1)
#pragma unroll
    for (int mf = 0; mf < 4; mf++) {
        int r0 = bm + wm * 64 + mf * 16 + g;
#pragma unroll
        for (int n8 = 0; n8 < 4; n8++) {
            int c0 = bn + wn * 32 + n8 * 8 + 2 * tg;
            if (OHALF) {
                __half* Ch = (__half*)Cout;
                *(uint32_t*)(Ch + (size_t)r0 * GN + c0) =
                    h2pack(acc[mf][n8][0] * cscale, acc[mf][n8][1] * cscale);
                *(uint32_t*)(Ch + (size_t)(r0 + 8) * GN + c0) =
                    h2pack(acc[mf][n8][2] * cscale, acc[mf][n8][3] * cscale);
            } else {
                float* Cf = (float*)Cout;
                *(float2*)(Cf + (size_t)r0 * GN + c0) =
                    make_float2(acc[mf][n8][0], acc[mf][n8][1]);
                *(float2*)(Cf + (size_t)(r0 + 8) * GN + c0) =
                    make_float2(acc[mf][n8][2], acc[mf][n8][3]);
            }
        }
    }
}

__global__ void __launch_bounds__(256) qkv_gemm_kernel()
{
    if (blockIdx.z == 0)      gemm_core<true>(g_qh, g_Wqh, g_Q, 0.125f);
    else if (blockIdx.z == 1) gemm_core<true>(g_kh, g_Wkh, g_K, 1.0f);
    else                      gemm_core<true>(g_vh, g_Wvh, g_V, 1.0f);
}

__global__ void __launch_bounds__(256) out_gemm_kernel(float* __restrict__ out)
{
    gemm_core<false>(g_O, g_Woh, out, 1.0f);
}

// ---------------------------------------------------------------------------
// Flash attention: fp16 m16n8k16, cp.async double-buffered K/V in NATURAL
// layout ([key][d], 144B row stride), ldmatrix for K (non-trans -> b-frags of
// K^T) and V (trans -> b-frags of V). Q frags register-hoisted. Warp-local
// softmax; FA2 identity keeps P in registers.
// ---------------------------------------------------------------------------
#define FROWB 144                       // 64 halves * 2B + 16B pad
#define FSTG  (64 * FROWB)              // 9216 bytes per K or V stage

__global__ void __launch_bounds__(128) flash_kernel()
{
    __shared__ __align__(16) uint32_t KV[2][2 * FSTG / 4];
    const uint32_t kvb = (uint32_t)__cvta_generic_to_shared(KV);
    uint32_t* KW = (uint32_t*)KV;       // word view for scalar loads

    const int tid  = threadIdx.x;
    const int w    = tid >> 5;
    const int lane = tid & 31;
    const int g    = lane >> 2;
    const int tg   = lane & 3;
    const int b    = blockIdx.z;
    const int h    = blockIdx.y;
    const int q0   = blockIdx.x * 128;
    const size_t base = ((size_t)b * SEQ) * HIDD + (size_t)h * HD;
    // ldmatrix lane mappings
    const int arow = (lane & 7) + ((lane >> 3) & 1) * 8;   // A / V-trans pattern
    const int achk = (lane >> 4) & 1;
    const int krow = (lane & 7) + ((lane >> 4) & 1) * 8;   // K non-trans pattern
    const int kchk = (lane >> 3) & 1;

    // ---- hoist Q fragments (Q pre-scaled): two 64-row passes via stage0 ----
    uint32_t qf[4][2][4];
#pragma unroll
    for (int ch = 0; ch < 2; ch++) {
#pragma unroll
        for (int t = 0; t < 4; t++) {
            int c = t * 128 + tid;
            int r = c >> 3, cq = c & 7;
            uint4 u = *(const uint4*)(&g_Q[base + (size_t)(q0 + ch * 64 + r) * HIDD + cq * 8]);
            *(uint4*)((char*)KV + r * FROWB + cq * 16) = u;
        }
        __syncthreads();
        if ((w >> 1) == ch) {
            int lr = (w & 1) * 32;
#pragma unroll
            for (int kk = 0; kk < 4; kk++)
#pragma unroll
                for (int mf = 0; mf < 2; mf++) {
                    int r0 = lr + mf * 16 + g;
                    qf[kk][mf][0] = KW[(r0)     * 36 + 8 * kk + tg];
                    qf[kk][mf][1] = KW[(r0 + 8) * 36 + 8 * kk + tg];
                    qf[kk][mf][2] = KW[(r0)     * 36 + 8 * kk + tg + 4];
                    qf[kk][mf][3] = KW[(r0 + 8) * 36 + 8 * kk + tg + 4];
                }
        }
        __syncthreads();
    }

#define F_ISSUE(s, k0) do {                                                     \
        uint32_t ksb = kvb + (s) * 2 * FSTG;                                    \
        uint32_t vsb = ksb + FSTG;                                              \
        _Pragma("unroll")                                                       \
        for (int t = 0; t < 4; t++) {                                           \
            int c = t * 128 + tid; int r = c >> 3, cq = c & 7;                  \
            CPASYNC16(ksb + r * FROWB + cq * 16,                                \
                      g_K + base + (size_t)((k0) + r) * HIDD + cq * 8);         \
        }                                                                       \
        _Pragma("unroll")                                                       \
        for (int t = 0; t < 4; t++) {                                           \
            int c = t * 128 + tid; int r = c >> 3, cq = c & 7;                  \
            CPASYNC16(vsb + r * FROWB + cq * 16,                                \
                      g_V + base + (size_t)((k0) + r) * HIDD + cq * 8);         \
        }                                                                       \
        CPCOMMIT();                                                             \
    } while (0)

    float o[2][8][4] = {};
    float m[2][2] = {{-1e30f, -1e30f}, {-1e30f, -1e30f}};
    float l[2][2] = {{0.0f, 0.0f}, {0.0f, 0.0f}};

    F_ISSUE(0, 0);

    for (int it = 0; it < SEQ / 64; it++) {
        const int cur = it & 1;
        if (it + 1 < SEQ / 64) {
            F_ISSUE(cur ^ 1, (it + 1) * 64);
            CPWAIT1();
        } else {
            CPWAIT0();
        }
        __syncthreads();

        const uint32_t ksb = kvb + cur * 2 * FSTG;
        const uint32_t vsb = ksb + FSTG;

        // ---- S = Q @ K^T : 32 rows x 64 keys per warp, ldmatrix K frags ----
        float s[2][8][4] = {};
#pragma unroll
        for (int kk = 0; kk < 4; kk++) {
#pragma unroll
            for (int ng = 0; ng < 4; ng++) {
                uint32_t bq[4];
                LDSM4(bq, ksb + (ng * 16 + krow) * FROWB + (2 * kk + kchk) * 16);
                mma_f16(s[0][2 * ng],     qf[kk][0], bq);
                mma_f16(s[0][2 * ng + 1], qf[kk][0], bq + 2);
                mma_f16(s[1][2 * ng],     qf[kk][1], bq);
                mma_f16(s[1][2 * ng + 1], qf[kk][1], bq + 2);
            }
        }

        // ---- online softmax per row-frag (quad shuffles) ----
#pragma unroll
        for (int mf = 0; mf < 2; mf++) {
            float tlo = -1e30f, thi = -1e30f;
#pragma unroll
            for (int nf = 0; nf < 8; nf++) {
                tlo = fmaxf(tlo, fmaxf(s[mf][nf][0], s[mf][nf][1]));
                thi = fmaxf(thi, fmaxf(s[mf][nf][2], s[mf][nf][3]));
            }
            tlo = fmaxf(tlo, __shfl_xor_sync(0xffffffffu, tlo, 1));
            tlo = fmaxf(tlo, __shfl_xor_sync(0xffffffffu, tlo, 2));
            thi = fmaxf(thi, __shfl_xor_sync(0xffffffffu, thi, 1));
            thi = fmaxf(thi, __shfl_xor_sync(0xffffffffu, thi, 2));

            float mn_lo = fmaxf(m[mf][0], tlo);
            float mn_hi = fmaxf(m[mf][1], thi);
            float corr_lo = __expf(m[mf][0] - mn_lo);
            float corr_hi = __expf(m[mf][1] - mn_hi);
            m[mf][0] = mn_lo; m[mf][1] = mn_hi;

            float sum_lo = 0.0f, sum_hi = 0.0f;
#pragma unroll
            for (int nf = 0; nf < 8; nf++) {
                s[mf][nf][0] = __expf(s[mf][nf][0] - mn_lo);
                s[mf][nf][1] = __expf(s[mf][nf][1] - mn_lo);
                s[mf][nf][2] = __expf(s[mf][nf][2] - mn_hi);
                s[mf][nf][3] = __expf(s[mf][nf][3] - mn_hi);
                sum_lo += s[mf][nf][0] + s[mf][nf][1];
                sum_hi += s[mf][nf][2] + s[mf][nf][3];
            }
            sum_lo += __shfl_xor_sync(0xffffffffu, sum_lo, 1);
            sum_lo += __shfl_xor_sync(0xffffffffu, sum_lo, 2);
            sum_hi += __shfl_xor_sync(0xffffffffu, sum_hi, 1);
            sum_hi += __shfl_xor_sync(0xffffffffu, sum_hi, 2);
            l[mf][0] = l[mf][0] * corr_lo + sum_lo;
            l[mf][1] = l[mf][1] * corr_hi + sum_hi;

#pragma unroll
            for (int nf = 0; nf < 8; nf++) {
                o[mf][nf][0] *= corr_lo;  o[mf][nf][1] *= corr_lo;
                o[mf][nf][2] *= corr_hi;  o[mf][nf][3] *= corr_hi;
            }
        }

        // ---- O += P @ V : FA2 identity for P; V b-frags via ldmatrix.trans ----
#pragma unroll
        for (int kc = 0; kc < 4; kc++) {
            uint32_t af[2][4];
#pragma unroll
            for (int mf = 0; mf < 2; mf++) {
                af[mf][0] = h2pack(s[mf][2 * kc][0],     s[mf][2 * kc][1]);
                af[mf][1] = h2pack(s[mf][2 * kc][2],     s[mf][2 * kc][3]);
                af[mf][2] = h2pack(s[mf][2 * kc + 1][0], s[mf][2 * kc + 1][1]);
                af[mf][3] = h2pack(s[mf][2 * kc + 1][2], s[mf][2 * kc + 1][3]);
            }
#pragma unroll
            for (int nf2 = 0; nf2 < 4; nf2++) {
                uint32_t bq[4];
                LDSM4T(bq, vsb + (kc * 16 + arow) * FROWB + nf2 * 32 + achk * 16);
                mma_f16(o[0][2 * nf2],     af[0], bq);
                mma_f16(o[0][2 * nf2 + 1], af[0], bq + 2);
                mma_f16(o[1][2 * nf2],     af[1], bq);
                mma_f16(o[1][2 * nf2 + 1], af[1], bq + 2);
            }
        }
        __syncthreads();   // all warps done with cur before it's re-issued
    }
#undef F_ISSUE

    // ---- epilogue: normalize, write half O ----
#pragma unroll
    for (int mf = 0; mf < 2; mf++) {
        float inv0 = 1.0f / l[mf][0];
        float inv1 = 1.0f / l[mf][1];
        size_t row = (size_t)(q0 + w * 32 + mf * 16 + g);
#pragma unroll
        for (int nf = 0; nf < 8; nf++) {
            int col = nf * 8 + 2 * tg;
            *(uint32_t*)(&g_O[base + row * HIDD + col]) =
                h2pack(o[mf][nf][0] * inv0, o[mf][nf][1] * inv0);
            *(uint32_t*)(&g_O[base + (row + 8) * HIDD + col]) =
                h2pack(o[mf][nf][2] * inv1, o[mf][nf][3] * inv1);
        }
    }
}

// ---------------------------------------------------------------------------
// Launch: 4 dependent kernels, graph-capturable, allocation-free.
// ---------------------------------------------------------------------------
extern "C" void kernel_launch(void* const* d_in, const int* in_sizes, int n_in,
                              void* d_out, int out_size)
{
    const float* q  = (const float*)d_in[0];
    const float* k  = (const float*)d_in[1];
    const float* v  = (const float*)d_in[2];
    const float* Wq = (const float*)d_in[3];
    const float* Wk = (const float*)d_in[4];
    const float* Wv = (const float*)d_in[5];
    const float* Wo = (const float*)d_in[6];
    float* out = (float*)d_out;
    (void)in_sizes; (void)n_in; (void)out_size;

    cudaFuncSetAttribute(qkv_gemm_kernel,
                         cudaFuncAttributeMaxDynamicSharedMemorySize, GEMM_SMEM);
    cudaFuncSetAttribute(out_gemm_kernel,
                         cudaFuncAttributeMaxDynamicSharedMemorySize, GEMM_SMEM);

    dim3 gcvt(2048, 1, 7);
    convert_kernel<<<gcvt, 256>>>((const float4*)q, (const float4*)k,
                                  (const float4*)v, (const float4*)Wq,
                                  (const float4*)Wk, (const float4*)Wv,
                                  (const float4*)Wo);

    dim3 gproj(GN / 128, GM / 128, 3);          // 8 x 64 x 3
    qkv_gemm_kernel<<<gproj, 256, GEMM_SMEM>>>();

    dim3 gattn(SEQ / 128, NH, BATCH);           // 16 x 16 x 4
    flash_kernel<<<gattn, 128>>>();

    dim3 gout(GN / 128, GM / 128);              // 8 x 64
    out_gemm_kernel<<<gout, 256, GEMM_SMEM>>>(out);   // FIX: pass dynamic smem
}

// round 16
// speedup vs baseline: 8.2239x; 1.0878x over previous
#include <cuda_runtime.h>
#include <cuda_fp16.h>
#include <stdint.h>

// Problem constants
#define BATCH 4
#define SEQ   2048
#define HIDD  1024
#define NH    16
#define HD    64

#define GM (BATCH*SEQ)
#define GK HIDD
#define GN HIDD

// ---------------------------------------------------------------------------
// Scratch (__device__ globals; allocations forbidden). All fp16.
// ---------------------------------------------------------------------------
__device__ __half g_Q[BATCH*SEQ*HIDD];   // pre-scaled by 1/8 at projection
__device__ __half g_K[BATCH*SEQ*HIDD];
__device__ __half g_V[BATCH*SEQ*HIDD];
__device__ __half g_O[BATCH*SEQ*HIDD];
// fp16 copies of the fp32 harness inputs (made by convert_kernel)
__device__ __half g_qh[GM*GK];
__device__ __half g_kh[GM*GK];
__device__ __half g_vh[GM*GK];
__device__ __half g_Wqh[GK*GN];
__device__ __half g_Wkh[GK*GN];
__device__ __half g_Wvh[GK*GN];
__device__ __half g_Woh[GK*GN];

// ---------------------------------------------------------------------------
// Helpers
// ---------------------------------------------------------------------------
__device__ __forceinline__ void mma_f16(float* d, const uint32_t* a, const uint32_t* b) {
    asm volatile(
        "mma.sync.aligned.m16n8k16.row.col.f32.f16.f16.f32 "
        "{%0,%1,%2,%3}, {%4,%5,%6,%7}, {%8,%9}, {%0,%1,%2,%3};"
        : "+f"(d[0]), "+f"(d[1]), "+f"(d[2]), "+f"(d[3])
        : "r"(a[0]), "r"(a[1]), "r"(a[2]), "r"(a[3]), "r"(b[0]), "r"(b[1]));
}
__device__ __forceinline__ uint32_t h2pack(float lo, float hi) {
    __half2 h = __floats2half2_rn(lo, hi);
    return *reinterpret_cast<uint32_t*>(&h);
}
#define LDSM4(R, addr) \
    asm volatile("ldmatrix.sync.aligned.m8n8.x4.shared.b16 {%0,%1,%2,%3}, [%4];" \
                 : "=r"((R)[0]), "=r"((R)[1]), "=r"((R)[2]), "=r"((R)[3]) : "r"(addr))
#define LDSM4T(R, addr) \
    asm volatile("ldmatrix.sync.aligned.m8n8.x4.trans.shared.b16 {%0,%1,%2,%3}, [%4];" \
                 : "=r"((R)[0]), "=r"((R)[1]), "=r"((R)[2]), "=r"((R)[3]) : "r"(addr))
#define CPASYNC16(s, g) \
    asm volatile("cp.async.ca.shared.global [%0], [%1], 16;" :: "r"(s), "l"(g))
#define CPCOMMIT() asm volatile("cp.async.commit_group;" ::: "memory")
#define CPWAIT0()  asm volatile("cp.async.wait_group 0;" ::: "memory")

// ---------------------------------------------------------------------------
// Convert kernel: fp32 inputs/weights -> fp16 device copies (one pass).
// ---------------------------------------------------------------------------
__global__ void __launch_bounds__(256) convert_kernel(
    const float4* q, const float4* k, const float4* v,
    const float4* wq, const float4* wk, const float4* wv, const float4* wo)
{
    const float4* src; uint2* dst; int n4;
    switch (blockIdx.z) {
        case 0: src = q;  dst = (uint2*)g_qh;  n4 = GM*GK/4; break;
        case 1: src = k;  dst = (uint2*)g_kh;  n4 = GM*GK/4; break;
        case 2: src = v;  dst = (uint2*)g_vh;  n4 = GM*GK/4; break;
        case 3: src = wq; dst = (uint2*)g_Wqh; n4 = GK*GN/4; break;
        case 4: src = wk; dst = (uint2*)g_Wkh; n4 = GK*GN/4; break;
        case 5: src = wv; dst = (uint2*)g_Wvh; n4 = GK*GN/4; break;
        default: src = wo; dst = (uint2*)g_Woh; n4 = GK*GN/4; break;
    }
    for (int i = blockIdx.x * blockDim.x + threadIdx.x; i < n4;
         i += gridDim.x * blockDim.x) {
        float4 f = src[i];
        uint2 u;
        u.x = h2pack(f.x, f.y);
        u.y = h2pack(f.z, f.w);
        dst[i] = u;
    }
}

// ---------------------------------------------------------------------------
// FP16 GEMM, cp.async 2-stage TK=64 + ldmatrix, ONE barrier per iteration.
// C[M,N] = A[M,K] @ W[K,N], all half. CTA 128x128, 256 threads (8 warps 2x4),
// warp tile 64x32.
// Stage: A [128 rows x 128B +16 pad = 144B] = 18432, B [64 rows x 272B] = 17408.
// Loop order per iter: wait(own) -> barrier -> issue(next) -> compute(cur).
// Barrier at iter it+1 proves compute(it) done in all warps, so re-issuing
// into that stage after the barrier is safe.
// ---------------------------------------------------------------------------
#define STG_A     18432
#define STG_B     17408
#define STG_BYTES (STG_A + STG_B)       // 35840
#define GEMM_SMEM (2 * STG_BYTES)       // 71680

template<bool OHALF>
__device__ __forceinline__ void gemm_core(const __half* __restrict__ Ah,
                                          const __half* __restrict__ Wh,
                                          void* __restrict__ Cout,
                                          float cscale)
{
    extern __shared__ __align__(16) char smem[];
    const uint32_t sb = (uint32_t)__cvta_generic_to_shared(smem);

    const int tid  = threadIdx.x;
    const int w    = tid >> 5;
    const int lane = tid & 31;
    const int g    = lane >> 2;
    const int tg   = lane & 3;
    const int wm   = w >> 2;          // 0..1 -> 64 rows
    const int wn   = w & 3;           // 0..3 -> 32 cols
    const int bm   = blockIdx.y * 128;
    const int bn   = blockIdx.x * 128;
    const int arow = (lane & 7) + ((lane >> 3) & 1) * 8;
    const int achk = (lane >> 4) & 1;

    float acc[4][4][4] = {};

    // issue one 64-k stage: A 128x128B (4 cp/thread), B 64x256B (4 cp/thread)
#define G_ISSUE(s, k0) do {                                                     \
        uint32_t sA = sb + (s) * STG_BYTES;                                     \
        uint32_t sB = sA + STG_A;                                               \
        _Pragma("unroll")                                                       \
        for (int t = 0; t < 4; t++) {                                           \
            int c = t * 256 + tid; int r = c >> 3, col = c & 7;                 \
            CPASYNC16(sA + r * 144 + col * 16,                                  \
                      Ah + (size_t)(bm + r) * GK + (k0) + col * 8);             \
        }                                                                       \
        _Pragma("unroll")                                                       \
        for (int t = 0; t < 4; t++) {                                           \
            int c = t * 256 + tid; int r = c >> 4, cn = c & 15;                 \
            CPASYNC16(sB + r * 272 + cn * 16,                                   \
                      Wh + (size_t)((k0) + r) * GN + bn + cn * 8);              \
        }                                                                       \
        CPCOMMIT();                                                             \
    } while (0)

    G_ISSUE(0, 0);

    for (int it = 0; it < 16; it++) {
        const int cur = it & 1;
        CPWAIT0();                 // own copies for stage cur done
        __syncthreads();           // all warps' copies visible; compute(it-1) done
        if (it + 1 < 16) G_ISSUE(cur ^ 1, (it + 1) * 64);

        uint32_t sA = sb + cur * STG_BYTES;
        uint32_t sB = sA + STG_A;
#pragma unroll
        for (int kk = 0; kk < 4; kk++) {
            uint32_t a[4][4], bq[2][4];
#pragma unroll
            for (int mf = 0; mf < 4; mf++)
                LDSM4(a[mf], sA + (wm * 64 + mf * 16 + arow) * 144 + kk * 32 + achk * 16);
#pragma unroll
            for (int nf2 = 0; nf2 < 2; nf2++)
                LDSM4T(bq[nf2], sB + (kk * 16 + arow) * 272 + wn * 64 + nf2 * 32 + achk * 16);
#pragma unroll
            for (int mf = 0; mf < 4; mf++)
#pragma unroll
                for (int n8 = 0; n8 < 4; n8++)
                    mma_f16(acc[mf][n8], a[mf], &bq[n8 >> 1][(n8 & 1) * 2]);
        }
    }
#undef G_ISSUE

    // Epilogue: C-layout (rows g/g+8, cols 2tg,2tg+1)
#pragma unroll
    for (int mf = 0; mf < 4; mf++) {
        int r0 = bm + wm * 64 + mf * 16 + g;
#pragma unroll
        for (int n8 = 0; n8 < 4; n8++) {
            int c0 = bn + wn * 32 + n8 * 8 + 2 * tg;
            if (OHALF) {
                __half* Ch = (__half*)Cout;
                *(uint32_t*)(Ch + (size_t)r0 * GN + c0) =
                    h2pack(acc[mf][n8][0] * cscale, acc[mf][n8][1] * cscale);
                *(uint32_t*)(Ch + (size_t)(r0 + 8) * GN + c0) =
                    h2pack(acc[mf][n8][2] * cscale, acc[mf][n8][3] * cscale);
            } else {
                float* Cf = (float*)Cout;
                *(float2*)(Cf + (size_t)r0 * GN + c0) =
                    make_float2(acc[mf][n8][0], acc[mf][n8][1]);
                *(float2*)(Cf + (size_t)(r0 + 8) * GN + c0) =
                    make_float2(acc[mf][n8][2], acc[mf][n8][3]);
            }
        }
    }
}

__global__ void __launch_bounds__(256) qkv_gemm_kernel()
{
    if (blockIdx.z == 0)      gemm_core<true>(g_qh, g_Wqh, g_Q, 0.125f);
    else if (blockIdx.z == 1) gemm_core<true>(g_kh, g_Wkh, g_K, 1.0f);
    else                      gemm_core<true>(g_vh, g_Wvh, g_V, 1.0f);
}

__global__ void __launch_bounds__(256) out_gemm_kernel(float* __restrict__ out)
{
    gemm_core<false>(g_O, g_Woh, out, 1.0f);
}

// ---------------------------------------------------------------------------
// Flash attention: fp16 m16n8k16, cp.async double-buffered K/V natural layout,
// ldmatrix K (non-trans) / V (trans), Q frags register-hoisted, warp-local
// softmax, FA2 identity for P. ONE barrier per KV tile (same reorder as GEMM).
// ---------------------------------------------------------------------------
#define FROWB 144                       // 64 halves * 2B + 16B pad
#define FSTG  (64 * FROWB)              // 9216 bytes per K or V stage

__global__ void __launch_bounds__(128) flash_kernel()
{
    __shared__ __align__(16) uint32_t KV[2][2 * FSTG / 4];
    const uint32_t kvb = (uint32_t)__cvta_generic_to_shared(KV);
    uint32_t* KW = (uint32_t*)KV;       // word view for scalar loads

    const int tid  = threadIdx.x;
    const int w    = tid >> 5;
    const int lane = tid & 31;
    const int g    = lane >> 2;
    const int tg   = lane & 3;
    const int b    = blockIdx.z;
    const int h    = blockIdx.y;
    const int q0   = blockIdx.x * 128;
    const size_t base = ((size_t)b * SEQ) * HIDD + (size_t)h * HD;
    const int arow = (lane & 7) + ((lane >> 3) & 1) * 8;   // A / V-trans pattern
    const int achk = (lane >> 4) & 1;
    const int krow = (lane & 7) + ((lane >> 4) & 1) * 8;   // K non-trans pattern
    const int kchk = (lane >> 3) & 1;

    // ---- hoist Q fragments (Q pre-scaled): two 64-row passes via stage0 ----
    uint32_t qf[4][2][4];
#pragma unroll
    for (int ch = 0; ch < 2; ch++) {
#pragma unroll
        for (int t = 0; t < 4; t++) {
            int c = t * 128 + tid;
            int r = c >> 3, cq = c & 7;
            uint4 u = *(const uint4*)(&g_Q[base + (size_t)(q0 + ch * 64 + r) * HIDD + cq * 8]);
            *(uint4*)((char*)KV + r * FROWB + cq * 16) = u;
        }
        __syncthreads();
        if ((w >> 1) == ch) {
            int lr = (w & 1) * 32;
#pragma unroll
            for (int kk = 0; kk < 4; kk++)
#pragma unroll
                for (int mf = 0; mf < 2; mf++) {
                    int r0 = lr + mf * 16 + g;
                    qf[kk][mf][0] = KW[(r0)     * 36 + 8 * kk + tg];
                    qf[kk][mf][1] = KW[(r0 + 8) * 36 + 8 * kk + tg];
                    qf[kk][mf][2] = KW[(r0)     * 36 + 8 * kk + tg + 4];
                    qf[kk][mf][3] = KW[(r0 + 8) * 36 + 8 * kk + tg + 4];
                }
        }
        __syncthreads();
    }

#define F_ISSUE(s, k0) do {                                                     \
        uint32_t ksb = kvb + (s) * 2 * FSTG;                                    \
        uint32_t vsb = ksb + FSTG;                                              \
        _Pragma("unroll")                                                       \
        for (int t = 0; t < 4; t++) {                                           \
            int c = t * 128 + tid; int r = c >> 3, cq = c & 7;                  \
            CPASYNC16(ksb + r * FROWB + cq * 16,                                \
                      g_K + base + (size_t)((k0) + r) * HIDD + cq * 8);         \
        }                                                                       \
        _Pragma("unroll")                                                       \
        for (int t = 0; t < 4; t++) {                                           \
            int c = t * 128 + tid; int r = c >> 3, cq = c & 7;                  \
            CPASYNC16(vsb + r * FROWB + cq * 16,                                \
                      g_V + base + (size_t)((k0) + r) * HIDD + cq * 8);         \
        }                                                                       \
        CPCOMMIT();                                                             \
    } while (0)

    float o[2][8][4] = {};
    float m[2][2] = {{-1e30f, -1e30f}, {-1e30f, -1e30f}};
    float l[2][2] = {{0.0f, 0.0f}, {0.0f, 0.0f}};

    F_ISSUE(0, 0);

    for (int it = 0; it < SEQ / 64; it++) {
        const int cur = it & 1;
        CPWAIT0();                 // own copies for stage cur done
        __syncthreads();           // all copies visible; compute(it-1) done
        if (it + 1 < SEQ / 64) F_ISSUE(cur ^ 1, (it + 1) * 64);

        const uint32_t ksb = kvb + cur * 2 * FSTG;
        const uint32_t vsb = ksb + FSTG;

        // ---- S = Q @ K^T : 32 rows x 64 keys per warp ----
        float s[2][8][4] = {};
#pragma unroll
        for (int kk = 0; kk < 4; kk++) {
#pragma unroll
            for (int ng = 0; ng < 4; ng++) {
                uint32_t bq[4];
                LDSM4(bq, ksb + (ng * 16 + krow) * FROWB + (2 * kk + kchk) * 16);
                mma_f16(s[0][2 * ng],     qf[kk][0], bq);
                mma_f16(s[0][2 * ng + 1], qf[kk][0], bq + 2);
                mma_f16(s[1][2 * ng],     qf[kk][1], bq);
                mma_f16(s[1][2 * ng + 1], qf[kk][1], bq + 2);
            }
        }

        // ---- online softmax per row-frag (quad shuffles) ----
#pragma unroll
        for (int mf = 0; mf < 2; mf++) {
            float tlo = -1e30f, thi = -1e30f;
#pragma unroll
            for (int nf = 0; nf < 8; nf++) {
                tlo = fmaxf(tlo, fmaxf(s[mf][nf][0], s[mf][nf][1]));
                thi = fmaxf(thi, fmaxf(s[mf][nf][2], s[mf][nf][3]));
            }
            tlo = fmaxf(tlo, __shfl_xor_sync(0xffffffffu, tlo, 1));
            tlo = fmaxf(tlo, __shfl_xor_sync(0xffffffffu, tlo, 2));
            thi = fmaxf(thi, __shfl_xor_sync(0xffffffffu, thi, 1));
            thi = fmaxf(thi, __shfl_xor_sync(0xffffffffu, thi, 2));

            float mn_lo = fmaxf(m[mf][0], tlo);
            float mn_hi = fmaxf(m[mf][1], thi);
            float corr_lo = __expf(m[mf][0] - mn_lo);
            float corr_hi = __expf(m[mf][1] - mn_hi);
            m[mf][0] = mn_lo; m[mf][1] = mn_hi;

            float sum_lo = 0.0f, sum_hi = 0.0f;
#pragma unroll
            for (int nf = 0; nf < 8; nf++) {
                s[mf][nf][0] = __expf(s[mf][nf][0] - mn_lo);
                s[mf][nf][1] = __expf(s[mf][nf][1] - mn_lo);
                s[mf][nf][2] = __expf(s[mf][nf][2] - mn_hi);
                s[mf][nf][3] = __expf(s[mf][nf][3] - mn_hi);
                sum_lo += s[mf][nf][0] + s[mf][nf][1];
                sum_hi += s[mf][nf][2] + s[mf][nf][3];
            }
            sum_lo += __shfl_xor_sync(0xffffffffu, sum_lo, 1);
            sum_lo += __shfl_xor_sync(0xffffffffu, sum_lo, 2);
            sum_hi += __shfl_xor_sync(0xffffffffu, sum_hi, 1);
            sum_hi += __shfl_xor_sync(0xffffffffu, sum_hi, 2);
            l[mf][0] = l[mf][0] * corr_lo + sum_lo;
            l[mf][1] = l[mf][1] * corr_hi + sum_hi;

#pragma unroll
            for (int nf = 0; nf < 8; nf++) {
                o[mf][nf][0] *= corr_lo;  o[mf][nf][1] *= corr_lo;
                o[mf][nf][2] *= corr_hi;  o[mf][nf][3] *= corr_hi;
            }
        }

        // ---- O += P @ V : FA2 identity for P; V b-frags via ldmatrix.trans ----
#pragma unroll
        for (int kc = 0; kc < 4; kc++) {
            uint32_t af[2][4];
#pragma unroll
            for (int mf = 0; mf < 2; mf++) {
                af[mf][0] = h2pack(s[mf][2 * kc][0],     s[mf][2 * kc][1]);
                af[mf][1] = h2pack(s[mf][2 * kc][2],     s[mf][2 * kc][3]);
                af[mf][2] = h2pack(s[mf][2 * kc + 1][0], s[mf][2 * kc + 1][1]);
                af[mf][3] = h2pack(s[mf][2 * kc + 1][2], s[mf][2 * kc + 1][3]);
            }
#pragma unroll
            for (int nf2 = 0; nf2 < 4; nf2++) {
                uint32_t bq[4];
                LDSM4T(bq, vsb + (kc * 16 + arow) * FROWB + nf2 * 32 + achk * 16);
                mma_f16(o[0][2 * nf2],     af[0], bq);
                mma_f16(o[0][2 * nf2 + 1], af[0], bq + 2);
                mma_f16(o[1][2 * nf2],     af[1], bq);
                mma_f16(o[1][2 * nf2 + 1], af[1], bq + 2);
            }
        }
    }
#undef F_ISSUE

    // ---- epilogue: normalize, write half O ----
#pragma unroll
    for (int mf = 0; mf < 2; mf++) {
        float inv0 = 1.0f / l[mf][0];
        float inv1 = 1.0f / l[mf][1];
        size_t row = (size_t)(q0 + w * 32 + mf * 16 + g);
#pragma unroll
        for (int nf = 0; nf < 8; nf++) {
            int col = nf * 8 + 2 * tg;
            *(uint32_t*)(&g_O[base + row * HIDD + col]) =
                h2pack(o[mf][nf][0] * inv0, o[mf][nf][1] * inv0);
            *(uint32_t*)(&g_O[base + (row + 8) * HIDD + col]) =
                h2pack(o[mf][nf][2] * inv1, o[mf][nf][3] * inv1);
        }
    }
}

// ---------------------------------------------------------------------------
// Launch: 4 dependent kernels, graph-capturable, allocation-free.
// ---------------------------------------------------------------------------
extern "C" void kernel_launch(void* const* d_in, const int* in_sizes, int n_in,
                              void* d_out, int out_size)
{
    const float* q  = (const float*)d_in[0];
    const float* k  = (const float*)d_in[1];
    const float* v  = (const float*)d_in[2];
    const float* Wq = (const float*)d_in[3];
    const float* Wk = (const float*)d_in[4];
    const float* Wv = (const float*)d_in[5];
    const float* Wo = (const float*)d_in[6];
    float* out = (float*)d_out;
    (void)in_sizes; (void)n_in; (void)out_size;

    cudaFuncSetAttribute(qkv_gemm_kernel,
                         cudaFuncAttributeMaxDynamicSharedMemorySize, GEMM_SMEM);
    cudaFuncSetAttribute(out_gemm_kernel,
                         cudaFuncAttributeMaxDynamicSharedMemorySize, GEMM_SMEM);

    dim3 gcvt(2048, 1, 7);
    convert_kernel<<<gcvt, 256>>>((const float4*)q, (const float4*)k,
                                  (const float4*)v, (const float4*)Wq,
                                  (const float4*)Wk, (const float4*)Wv,
                                  (const float4*)Wo);

    dim3 gproj(GN / 128, GM / 128, 3);          // 8 x 64 x 3
    qkv_gemm_kernel<<<gproj, 256, GEMM_SMEM>>>();

    dim3 gattn(SEQ / 128, NH, BATCH);           // 16 x 16 x 4
    flash_kernel<<<gattn, 128>>>();

    dim3 gout(GN / 128, GM / 128);              // 8 x 64
    out_gemm_kernel<<<gout, 256, GEMM_SMEM>>>(out);
}